// round 6
// baseline (speedup 1.0000x reference)
#include <cuda_runtime.h>
#include <cuda_bf16.h>
#include <math.h>
#include <stdint.h>

#define Bsz 4
#define SEQ 4096
#define WID 768
#define NH  12
#define MBm 16
#define NBt 256           // SEQ / MBm
#define EPSV 1e-6f
#define MTOT (Bsz*SEQ)    // 16384
#define WW   (WID*WID)

// ------------------------- scratch (device globals) -------------------------
__device__ __align__(16) float g_xqk [Bsz*SEQ*WID];
__device__ __align__(16) float g_xv  [Bsz*SEQ*WID];
__device__ __align__(16) float g_gate[Bsz*SEQ*WID];
__device__ __align__(16) float g_ttt [Bsz*SEQ*WID];
__device__ __align__(16) float g_lr  [Bsz*NH*SEQ];
__device__ __align__(16) __nv_bfloat16 g_hh[Bsz*SEQ*WID];
__device__ __align__(16) __nv_bfloat16 g_hl[Bsz*SEQ*WID];
__device__ __align__(16) __nv_bfloat16 g_th[Bsz*SEQ*WID];
__device__ __align__(16) __nv_bfloat16 g_tl[Bsz*SEQ*WID];
__device__ __align__(16) __nv_bfloat16 g_wt[8*WW];

// ------------------------- helpers -------------------------
__device__ __forceinline__ uint32_t smem_u32(const void* p) {
    uint32_t a;
    asm("{ .reg .u64 t; cvta.to.shared.u64 t, %1; cvt.u32.u64 %0, t; }" : "=r"(a) : "l"(p));
    return a;
}
__device__ __forceinline__ float wred(float v) {
#pragma unroll
    for (int o = 16; o; o >>= 1) v += __shfl_xor_sync(0xffffffffu, v, o);
    return v;
}
__device__ __forceinline__ float hred(float v) {
#pragma unroll
    for (int o = 8; o; o >>= 1) v += __shfl_xor_sync(0xffffffffu, v, o);
    return v;
}
__device__ __forceinline__ unsigned long long pk2(float lo, float hi) {
    unsigned long long r;
    asm("mov.b64 %0, {%1, %2};" : "=l"(r) : "f"(lo), "f"(hi));
    return r;
}
__device__ __forceinline__ void fma2(unsigned long long& acc,
                                     unsigned long long a, unsigned long long b) {
    asm("fma.rn.f32x2 %0, %1, %2, %0;" : "+l"(acc) : "l"(a), "l"(b));
}
__device__ __forceinline__ float2 up2(unsigned long long v) {
    float lo, hi;
    asm("mov.b64 {%0, %1}, %2;" : "=f"(lo), "=f"(hi) : "l"(v));
    return make_float2(lo, hi);
}
__device__ __forceinline__ void cpa16(uint32_t saddr, const void* g) {
    asm volatile("cp.async.cg.shared.global [%0], [%1], 16;" :: "r"(saddr), "l"(g) : "memory");
}
__device__ __forceinline__ void cpa_commit() {
    asm volatile("cp.async.commit_group;" ::: "memory");
}
__device__ __forceinline__ void ldsm4(uint32_t& r0, uint32_t& r1, uint32_t& r2, uint32_t& r3, uint32_t a) {
    asm volatile("ldmatrix.sync.aligned.m8n8.x4.shared.b16 {%0,%1,%2,%3}, [%4];"
                 : "=r"(r0), "=r"(r1), "=r"(r2), "=r"(r3) : "r"(a));
}
__device__ __forceinline__ void mma16816(float* c, const uint32_t* a, const uint32_t* b) {
    asm volatile("mma.sync.aligned.m16n8k16.row.col.f32.bf16.bf16.f32 "
                 "{%0,%1,%2,%3}, {%4,%5,%6,%7}, {%8,%9}, {%0,%1,%2,%3};"
                 : "+f"(c[0]), "+f"(c[1]), "+f"(c[2]), "+f"(c[3])
                 : "r"(a[0]), "r"(a[1]), "r"(a[2]), "r"(a[3]), "r"(b[0]), "r"(b[1]));
}

// --------- prep kernel: lr logits (blocks [0,2048)) + weight cvt (rest) -----
__global__ __launch_bounds__(256) void prep_kernel(
    const float* __restrict__ hidden, const float* __restrict__ lrk,
    const float* __restrict__ lrb,
    const float* __restrict__ w0, const float* __restrict__ w1,
    const float* __restrict__ w2, const float* __restrict__ w3)
{
    __shared__ float sk[NH * WID];
    __shared__ float tile[32][33];
    const int tid = threadIdx.x;

    if (blockIdx.x < 2048) {
        for (int i = tid; i < NH * WID; i += 256) sk[i] = lrk[i];
        __syncthreads();
        const int gw = blockIdx.x * 8 + (tid >> 5);
        const int lane = tid & 31;
        const float* hrow = hidden + (size_t)gw * WID;
        float acc[NH];
#pragma unroll
        for (int h = 0; h < NH; h++) acc[h] = 0.f;
        for (int w = lane; w < WID; w += 32) {
            float hv = hrow[w];
#pragma unroll
            for (int h = 0; h < NH; h++) acc[h] += hv * sk[h * WID + w];
        }
        const int b = gw >> 12, n = gw & (SEQ - 1);
#pragma unroll
        for (int h = 0; h < NH; h++) {
            float v = wred(acc[h]);
            if (lane == 0) {
                float x = v + lrb[h];
                g_lr[(size_t)(b * NH + h) * SEQ + n] = (1.f / (1.f + expf(-x))) * (1.f / 64.f);
            }
        }
    } else {
        const int bi = blockIdx.x - 2048;
        const int z = bi / 576;
        const int rem = bi % 576;
        const float* w = (z == 0) ? w0 : (z == 1) ? w1 : (z == 2) ? w2 : w3;
        __nv_bfloat16* th = g_wt + ((z < 3) ? (size_t)z * WW : (size_t)6 * WW);
        __nv_bfloat16* tl = g_wt + ((z < 3) ? (size_t)(3 + z) * WW : (size_t)7 * WW);
        const int bx = (rem % 24) * 32;
        const int by = (rem / 24) * 32;
        const int x = tid & 31, y = tid >> 5;
#pragma unroll
        for (int j = 0; j < 4; j++)
            tile[y + j * 8][x] = w[(size_t)(by + y + j * 8) * WID + bx + x];
        __syncthreads();
#pragma unroll
        for (int j = 0; j < 4; j++) {
            float v = tile[x][y + j * 8];
            __nv_bfloat16 hh = __float2bfloat16(v);
            size_t o = (size_t)(bx + y + j * 8) * WID + by + x;
            th[o] = hh;
            tl[o] = __float2bfloat16(v - __bfloat162float(hh));
        }
    }
}

// ------------------------- fp32 -> bf16 hi/lo split --------------------------
__global__ __launch_bounds__(256) void cvt_hilo_kernel(
    const float* __restrict__ x, __nv_bfloat16* __restrict__ hi,
    __nv_bfloat16* __restrict__ lo, int n4)
{
    int i = blockIdx.x * 256 + threadIdx.x;
    if (i >= n4) return;
    float4 v = ((const float4*)x)[i];
    __nv_bfloat16 h0 = __float2bfloat16(v.x), h1 = __float2bfloat16(v.y);
    __nv_bfloat16 h2 = __float2bfloat16(v.z), h3 = __float2bfloat16(v.w);
    __nv_bfloat16 l0 = __float2bfloat16(v.x - __bfloat162float(h0));
    __nv_bfloat16 l1 = __float2bfloat16(v.y - __bfloat162float(h1));
    __nv_bfloat16 l2 = __float2bfloat16(v.z - __bfloat162float(h2));
    __nv_bfloat16 l3 = __float2bfloat16(v.w - __bfloat162float(h3));
    __nv_bfloat162 ph0(h0, h1), ph1(h2, h3), pl0(l0, l1), pl1(l2, l3);
    ((uint2*)hi)[i] = make_uint2(*(unsigned*)&ph0, *(unsigned*)&ph1);
    ((uint2*)lo)[i] = make_uint2(*(unsigned*)&pl0, *(unsigned*)&pl1);
}

// ------------------------- bf16-split GEMM via mma.sync ----------------------
#define TSTRIDE 40
#define TILEB  (128*TSTRIDE*2)
#define STAGEB (4*TILEB)

__global__ __launch_bounds__(256) void mma_gemm_kernel(
    const __nv_bfloat16* __restrict__ Ah, const __nv_bfloat16* __restrict__ Al,
    const __nv_bfloat16* __restrict__ Bh, const __nv_bfloat16* __restrict__ Bl,
    float* __restrict__ C0, float* __restrict__ C1, float* __restrict__ C2)
{
    extern __shared__ char smem[];
    const uint32_t sb = smem_u32(smem);
    const int tid = threadIdx.x, wid = tid >> 5, lane = tid & 31;
    const int bm = blockIdx.y * 128;
    const int bn = blockIdx.x * 128;
    const int buf = blockIdx.x / 6;
    const int coloff = (blockIdx.x % 6) * 128;
    float* C = (buf == 0) ? C0 : (buf == 1) ? C1 : C2;
    const int warpM = wid & 3, warpN = wid >> 2;

    const __nv_bfloat16* srcs[4] = {
        Ah + (size_t)bm * WID, Al + (size_t)bm * WID,
        Bh + (size_t)bn * WID, Bl + (size_t)bn * WID };

    auto load_stage = [&](int st, int k0) {
#pragma unroll
        for (int t = 0; t < 4; t++) {
#pragma unroll
            for (int rep = 0; rep < 2; rep++) {
                int li = tid + rep * 256;
                int row = li >> 2, cc = li & 3;
                const void* g = srcs[t] + (size_t)row * WID + k0 + cc * 8;
                uint32_t sa = sb + st * STAGEB + t * TILEB + row * (TSTRIDE * 2) + cc * 16;
                cpa16(sa, g);
            }
        }
        cpa_commit();
    };

    float acc[2][8][4];
#pragma unroll
    for (int i = 0; i < 2; i++)
#pragma unroll
        for (int j = 0; j < 8; j++)
#pragma unroll
            for (int k = 0; k < 4; k++) acc[i][j][k] = 0.f;

    load_stage(0, 0);

    const int NK = WID / 32;
    for (int kt = 0; kt < NK; kt++) {
        if (kt + 1 < NK) load_stage((kt + 1) & 1, (kt + 1) * 32);
        if (kt + 1 < NK) asm volatile("cp.async.wait_group 1;" ::: "memory");
        else             asm volatile("cp.async.wait_group 0;" ::: "memory");
        __syncthreads();

        const uint32_t base = sb + (kt & 1) * STAGEB;
        const int lrow = lane & 15;
        const int lcol = (lane & 16) ? 8 : 0;

#pragma unroll
        for (int kk = 0; kk < 2; kk++) {
            const int kb = kk * 16;
            uint32_t ah[2][4], al[2][4], bh[8][2], bl[8][2];
#pragma unroll
            for (int mt = 0; mt < 2; mt++) {
                uint32_t off = (uint32_t)((warpM * 32 + mt * 16 + lrow) * TSTRIDE + kb + lcol) * 2;
                ldsm4(ah[mt][0], ah[mt][1], ah[mt][2], ah[mt][3], base + 0 * TILEB + off);
                ldsm4(al[mt][0], al[mt][1], al[mt][2], al[mt][3], base + 1 * TILEB + off);
            }
#pragma unroll
            for (int ng = 0; ng < 4; ng++) {
                uint32_t off = (uint32_t)((warpN * 64 + ng * 16 + lrow) * TSTRIDE + kb + lcol) * 2;
                uint32_t r0, r1, r2, r3;
                ldsm4(r0, r1, r2, r3, base + 2 * TILEB + off);
                bh[ng * 2][0] = r0; bh[ng * 2 + 1][0] = r1;
                bh[ng * 2][1] = r2; bh[ng * 2 + 1][1] = r3;
                ldsm4(r0, r1, r2, r3, base + 3 * TILEB + off);
                bl[ng * 2][0] = r0; bl[ng * 2 + 1][0] = r1;
                bl[ng * 2][1] = r2; bl[ng * 2 + 1][1] = r3;
            }
#pragma unroll
            for (int mt = 0; mt < 2; mt++)
#pragma unroll
                for (int nt = 0; nt < 8; nt++) {
                    mma16816(acc[mt][nt], ah[mt], bh[nt]);
                    mma16816(acc[mt][nt], ah[mt], bl[nt]);
                    mma16816(acc[mt][nt], al[mt], bh[nt]);
                }
        }
        __syncthreads();
    }

    const int r0 = bm + warpM * 32 + (lane >> 2);
    const int cb = coloff + warpN * 64 + 2 * (lane & 3);
#pragma unroll
    for (int mt = 0; mt < 2; mt++)
#pragma unroll
        for (int nt = 0; nt < 8; nt++) {
            int row = r0 + mt * 16, col = cb + nt * 8;
            *(float2*)(C + (size_t)row * WID + col) = make_float2(acc[mt][nt][0], acc[mt][nt][1]);
            *(float2*)(C + (size_t)(row + 8) * WID + col) = make_float2(acc[mt][nt][2], acc[mt][nt][3]);
        }
}

// ------------------------- TTT scan (512 threads) ---------------------------
// team = tid>>8. Row layout (conv/LN/Cf/output): r=t>>4, cg=t&15.
// GEMM layout (transposed): rG=t&15, cG=t>>4 -> warp touches only 2 W1 lines/iter.
// P1: team0 Z1=XK@W1, team1 ZQ=XQ@W1 (full K each, no reduction).
// P2: team0 LN+grad -> sG ; team1 Cf. P3: team0 Z1_bar+out ; team1 W1/b1 update.
__global__ __launch_bounds__(512) void ttt_scan_kernel(
    const float* __restrict__ W1in, const float* __restrict__ b1in,
    const float* __restrict__ gin,  const float* __restrict__ bbin,
    const float* __restrict__ lti,
    const float* __restrict__ cqk, const float* __restrict__ cqb,
    const float* __restrict__ ckk, const float* __restrict__ ckb)
{
    __shared__ float W1s[64 * 64];
    __shared__ float b1s[64];
    __shared__ float sXQ[16 * 68], sXK[16 * 68], sG[16 * 68];
    __shared__ float sZ[16 * 68], sZQ[16 * 68];
    __shared__ float Cf[256];
    __shared__ float lr[16], lrw[16], toki[16];

    const int tid = threadIdx.x;
    const int bh = blockIdx.x;
    const int b = bh / NH, h = bh % NH;
    const bool t0 = (tid < 256);
    const int t = tid & 255;

    for (int i = tid; i < 4096; i += 512) W1s[i] = W1in[h * 4096 + i];
    if (tid < 64) b1s[tid] = b1in[h * 64 + tid];
    if (tid < 16) toki[tid] = fmaxf(1.f / (float)(tid + 1) + lti[tid], 0.f);

    const int r  = t >> 4;          // row layout
    const int cg = t & 15;
    const int c0 = cg * 4;
    const int rG  = t & 15;         // GEMM layout
    const int c0G = (t >> 4) * 4;

    const size_t gb2 = (size_t)b * SEQ * WID + h * 64 + c0;
    const float* lrp = g_lr + (size_t)bh * SEQ;

    // team-0 constants
    float4 wq0, wq1, wq2, wq3, wk0, wk1, wk2, wk3, qb4, kb4;
    float cs0 = 0.f, sn0 = 0.f, cs1 = 0.f, sn1 = 0.f;
    float gv0 = 0.f, gv1 = 0.f, gv2 = 0.f, gv3 = 0.f;
    float bv0 = 0.f, bv1 = 0.f, bv2 = 0.f, bv3 = 0.f;
    if (t0) {
        wq0 = *(const float4*)(cqk + 0 * WID + h * 64 + c0);
        wq1 = *(const float4*)(cqk + 1 * WID + h * 64 + c0);
        wq2 = *(const float4*)(cqk + 2 * WID + h * 64 + c0);
        wq3 = *(const float4*)(cqk + 3 * WID + h * 64 + c0);
        wk0 = *(const float4*)(ckk + 0 * WID + h * 64 + c0);
        wk1 = *(const float4*)(ckk + 1 * WID + h * 64 + c0);
        wk2 = *(const float4*)(ckk + 2 * WID + h * 64 + c0);
        wk3 = *(const float4*)(ckk + 3 * WID + h * 64 + c0);
        qb4 = *(const float4*)(cqb + h * 64 + c0);
        kb4 = *(const float4*)(ckb + h * 64 + c0);
        int j0 = c0 >> 1;
        float f0 = expf(-9.210340371976184f * (float)j0 * (1.f / 32.f));
        float f1 = expf(-9.210340371976184f * (float)(j0 + 1) * (1.f / 32.f));
        cs0 = cosf((float)r * f0); sn0 = sinf((float)r * f0);
        cs1 = cosf((float)r * f1); sn1 = sinf((float)r * f1);
        gv0 = gin[h * 64 + c0];     gv1 = gin[h * 64 + c0 + 1];
        gv2 = gin[h * 64 + c0 + 2]; gv3 = gin[h * 64 + c0 + 3];
        bv0 = bbin[h * 64 + c0];     bv1 = bbin[h * 64 + c0 + 1];
        bv2 = bbin[h * 64 + c0 + 2]; bv3 = bbin[h * 64 + c0 + 3];
    }
    __syncthreads();
    const float tokir  = toki[r];
    const float toki15 = toki[15];

    // prologue prefetch (tile nb=0) — team0 only
    float4 x0n = make_float4(0, 0, 0, 0), x1n = x0n, x2n = x0n, x3n = x0n, v4n = x0n;
    float lrn = 0.f;
    if (t0) {
        if (r >= 3) x0n = *(const float4*)(g_xqk + gb2 + (size_t)(r - 3) * WID);
        if (r >= 2) x1n = *(const float4*)(g_xqk + gb2 + (size_t)(r - 2) * WID);
        if (r >= 1) x2n = *(const float4*)(g_xqk + gb2 + (size_t)(r - 1) * WID);
        x3n = *(const float4*)(g_xqk + gb2 + (size_t)r * WID);
        v4n = *(const float4*)(g_xv + gb2 + (size_t)r * WID);
    } else if (t < 16) {
        lrn = lrp[t];
    }

    float4 q4c = make_float4(0, 0, 0, 0), t4c = q4c;

    for (int nb = 0; nb < NBt; nb++) {
        __syncthreads();                                   // (A) prior step done
        if (t0) {
            float4 q, k;
            q.x = qb4.x + x0n.x * wq0.x + x1n.x * wq1.x + x2n.x * wq2.x + x3n.x * wq3.x;
            q.y = qb4.y + x0n.y * wq0.y + x1n.y * wq1.y + x2n.y * wq2.y + x3n.y * wq3.y;
            q.z = qb4.z + x0n.z * wq0.z + x1n.z * wq1.z + x2n.z * wq2.z + x3n.z * wq3.z;
            q.w = qb4.w + x0n.w * wq0.w + x1n.w * wq1.w + x2n.w * wq2.w + x3n.w * wq3.w;
            k.x = kb4.x + x0n.x * wk0.x + x1n.x * wk1.x + x2n.x * wk2.x + x3n.x * wk3.x;
            k.y = kb4.y + x0n.y * wk0.y + x1n.y * wk1.y + x2n.y * wk2.y + x3n.y * wk3.y;
            k.z = kb4.z + x0n.z * wk0.z + x1n.z * wk1.z + x2n.z * wk2.z + x3n.z * wk3.z;
            k.w = kb4.w + x0n.w * wk0.w + x1n.w * wk1.w + x2n.w * wk2.w + x3n.w * wk3.w;
            float4 qr, kr;
            qr.x = q.x * cs0 - q.y * sn0; qr.y = q.x * sn0 + q.y * cs0;
            qr.z = q.z * cs1 - q.w * sn1; qr.w = q.z * sn1 + q.w * cs1;
            kr.x = k.x * cs0 - k.y * sn0; kr.y = k.x * sn0 + k.y * cs0;
            kr.z = k.z * cs1 - k.w * sn1; kr.w = k.z * sn1 + k.w * cs1;
            *(float4*)(sXQ + r * 68 + c0) = qr;
            *(float4*)(sXK + r * 68 + c0) = kr;
            q4c = qr;
            t4c = make_float4(v4n.x - kr.x, v4n.y - kr.y, v4n.z - kr.z, v4n.w - kr.w);
        } else if (t < 16) {
            lr[t] = lrn; lrw[t] = toki15 * lrn;
        }
        __syncthreads();                                   // (B) tiles ready

        // prefetch next tile
        if (nb + 1 < NBt) {
            if (t0) {
                const size_t rb = gb2 + (size_t)((nb + 1) * MBm + r - 3) * WID;
                x0n = *(const float4*)(g_xqk + rb);
                x1n = *(const float4*)(g_xqk + rb + WID);
                x2n = *(const float4*)(g_xqk + rb + 2 * WID);
                x3n = *(const float4*)(g_xqk + rb + 3 * WID);
                v4n = *(const float4*)(g_xv + rb + 3 * WID);
            } else if (t < 16) {
                lrn = lrp[(nb + 1) * MBm + t];
            }
        }

        // ---- P1: per-team full-K GEMM in transposed layout ----
        {
            const float* xrow = (t0 ? sXK : sXQ) + rG * 68;
            unsigned long long a0 = pk2(b1s[c0G], b1s[c0G + 1]);
            unsigned long long a1 = pk2(b1s[c0G + 2], b1s[c0G + 3]);
#pragma unroll
            for (int k4 = 0; k4 < 64; k4 += 4) {
                float4 x = *(const float4*)(xrow + k4);
                ulonglong2 w0 = *(const ulonglong2*)(W1s + (k4 + 0) * 64 + c0G);
                ulonglong2 w1 = *(const ulonglong2*)(W1s + (k4 + 1) * 64 + c0G);
                ulonglong2 w2 = *(const ulonglong2*)(W1s + (k4 + 2) * 64 + c0G);
                ulonglong2 w3 = *(const ulonglong2*)(W1s + (k4 + 3) * 64 + c0G);
                unsigned long long p0 = pk2(x.x, x.x), p1 = pk2(x.y, x.y);
                unsigned long long p2 = pk2(x.z, x.z), p3 = pk2(x.w, x.w);
                fma2(a0, p0, w0.x); fma2(a1, p0, w0.y);
                fma2(a0, p1, w1.x); fma2(a1, p1, w1.y);
                fma2(a0, p2, w2.x); fma2(a1, p2, w2.y);
                fma2(a0, p3, w3.x); fma2(a1, p3, w3.y);
            }
            float2 pA = up2(a0), pB = up2(a1);
            float* dst = (t0 ? sZ : sZQ) + rG * 68 + c0G;
            *(float4*)dst = make_float4(pA.x, pA.y, pB.x, pB.y);
        }
        __syncthreads();                                   // (B2) sZ/sZQ ready

        if (t0) {
            // P2a: LN-fused-L2-bwd on Z1 (row layout)
            float4 z4 = *(const float4*)(sZ + r * 68 + c0);
            float z0 = z4.x, z1 = z4.y, z2 = z4.z, z3 = z4.w;
            float s = hred(z0 + z1 + z2 + z3);
            float qq = hred(z0 * z0 + z1 * z1 + z2 * z2 + z3 * z3);
            float m = s * (1.f / 64.f);
            float rstd = rsqrtf(qq * (1.f / 64.f) - m * m + EPSV);
            float xh0 = (z0 - m) * rstd, xh1 = (z1 - m) * rstd;
            float xh2 = (z2 - m) * rstd, xh3 = (z3 - m) * rstd;
            float gx0 = (gv0 * xh0 + bv0 - t4c.x) * gv0;
            float gx1 = (gv1 * xh1 + bv1 - t4c.y) * gv1;
            float gx2 = (gv2 * xh2 + bv2 - t4c.z) * gv2;
            float gx3 = (gv3 * xh3 + bv3 - t4c.w) * gv3;
            float s1 = hred(gx0 + gx1 + gx2 + gx3);
            float s2 = hred(gx0 * xh0 + gx1 * xh1 + gx2 * xh2 + gx3 * xh3);
            float sc = rstd * (1.f / 64.f);
            float4 gr;
            gr.x = (64.f * gx0 - s1 - xh0 * s2) * sc;
            gr.y = (64.f * gx1 - s1 - xh1 * s2) * sc;
            gr.z = (64.f * gx2 - s1 - xh2 * s2) * sc;
            gr.w = (64.f * gx3 - s1 - xh3 * s2) * sc;
            *(float4*)(sG + r * 68 + c0) = gr;
        } else {
            // P2b: Cf[i=r][m=cg] = toki[i]*lr[m]*(XQ[i].XK[m] + 1), m<=i
            float cf = 0.f;
            if (cg <= r) {
                unsigned long long acc = 0ULL;
#pragma unroll 8
                for (int kk = 0; kk < 32; kk++) {
                    unsigned long long a = *(const unsigned long long*)(sXQ + r * 68 + 2 * kk);
                    unsigned long long bb = *(const unsigned long long*)(sXK + cg * 68 + 2 * kk);
                    fma2(acc, a, bb);
                }
                float2 p = up2(acc);
                cf = tokir * lr[cg] * (p.x + p.y + 1.f);
            }
            Cf[r * 16 + cg] = cf;
        }
        __syncthreads();                                   // (C) sG + Cf ready

        if (t0) {
            // P3a: Z1_bar = ZQ - Cf@grad ; out = XQ + ln_fwd(Z1_bar)
            float4 yq = *(const float4*)(sZQ + r * 68 + c0);
            unsigned long long y01 = pk2(yq.x, yq.y);
            unsigned long long y23 = pk2(yq.z, yq.w);
#pragma unroll
            for (int mm = 0; mm < 16; mm++) {
                float nc = -Cf[r * 16 + mm];
                unsigned long long pc = pk2(nc, nc);
                ulonglong2 g = *(const ulonglong2*)(sG + mm * 68 + c0);
                fma2(y01, pc, g.x); fma2(y23, pc, g.y);
            }
            float2 pA = up2(y01), pB = up2(y23);
            float y0 = pA.x, y1 = pA.y, y2 = pB.x, y3 = pB.y;
            float s = hred(y0 + y1 + y2 + y3);
            float qq = hred(y0 * y0 + y1 * y1 + y2 * y2 + y3 * y3);
            float m = s * (1.f / 64.f);
            float rstd = rsqrtf(qq * (1.f / 64.f) - m * m + EPSV);
            float4 o;
            o.x = q4c.x + gv0 * ((y0 - m) * rstd) + bv0;
            o.y = q4c.y + gv1 * ((y1 - m) * rstd) + bv1;
            o.z = q4c.z + gv2 * ((y2 - m) * rstd) + bv2;
            o.w = q4c.w + gv3 * ((y3 - m) * rstd) + bv3;
            *(float4*)(g_ttt + gb2 + (size_t)(nb * MBm + r) * WID) = o;
        } else {
            // P3b: W1 -= XK^T @ (lrw*G); b1 -= col sums
            const int d = t & 63;
            const int kbase = (t >> 6) * 16;
            float gvv[16];
            float bs = 0.f;
#pragma unroll
            for (int mm = 0; mm < 16; mm++) {
                gvv[mm] = lrw[mm] * sG[mm * 68 + d];
                bs += gvv[mm];
            }
            unsigned long long acc[8];
#pragma unroll
            for (int j = 0; j < 8; j++) acc[j] = 0ULL;
#pragma unroll
            for (int mm = 0; mm < 16; mm++) {
                unsigned long long gp = pk2(gvv[mm], gvv[mm]);
                ulonglong2 xx0 = *(const ulonglong2*)(sXK + mm * 68 + kbase);
                ulonglong2 xx1 = *(const ulonglong2*)(sXK + mm * 68 + kbase + 4);
                ulonglong2 xx2 = *(const ulonglong2*)(sXK + mm * 68 + kbase + 8);
                ulonglong2 xx3 = *(const ulonglong2*)(sXK + mm * 68 + kbase + 12);
                fma2(acc[0], gp, xx0.x); fma2(acc[1], gp, xx0.y);
                fma2(acc[2], gp, xx1.x); fma2(acc[3], gp, xx1.y);
                fma2(acc[4], gp, xx2.x); fma2(acc[5], gp, xx2.y);
                fma2(acc[6], gp, xx3.x); fma2(acc[7], gp, xx3.y);
            }
#pragma unroll
            for (int j = 0; j < 8; j++) {
                float2 p = up2(acc[j]);
                int k0 = kbase + 2 * j;
                W1s[k0 * 64 + d]       -= p.x;
                W1s[(k0 + 1) * 64 + d] -= p.y;
            }
            if (t < 64) b1s[t] -= bs;
        }
    }
}

// ------------------------- post: t = gelu(gate) * LN(out) -> bf16 hi/lo -----
__global__ __launch_bounds__(256) void postfuse_kernel(
    const float* __restrict__ pns, const float* __restrict__ pnb)
{
    __shared__ float ws[8], wq2[8];
    __shared__ float smu, srs;
    const int row = blockIdx.x;
    const int tid = threadIdx.x;
    const int lane = tid & 31, wid = tid >> 5;
    const float* o = g_ttt + (size_t)row * WID;
    const float* gp = g_gate + (size_t)row * WID;

    float v[3], s = 0.f, q = 0.f;
#pragma unroll
    for (int i = 0; i < 3; i++) {
        v[i] = o[tid + i * 256];
        s += v[i]; q += v[i] * v[i];
    }
    s = wred(s); q = wred(q);
    if (lane == 0) { ws[wid] = s; wq2[wid] = q; }
    __syncthreads();
    if (tid == 0) {
        float S = 0.f, Q = 0.f;
#pragma unroll
        for (int i = 0; i < 8; i++) { S += ws[i]; Q += wq2[i]; }
        float m = S * (1.f / 768.f);
        smu = m;
        srs = rsqrtf(Q * (1.f / 768.f) - m * m + EPSV);
    }
    __syncthreads();
    const float m = smu, rs = srs;
#pragma unroll
    for (int i = 0; i < 3; i++) {
        int c = tid + i * 256;
        float z = pns[c] * ((v[i] - m) * rs) + pnb[c];
        float x = gp[c];
        float gl = 0.5f * x * (1.f + tanhf(0.7978845608028654f * (x + 0.044715f * x * x * x)));
        float val = gl * z;
        __nv_bfloat16 hi = __float2bfloat16(val);
        g_th[(size_t)row * WID + c] = hi;
        g_tl[(size_t)row * WID + c] = __float2bfloat16(val - __bfloat162float(hi));
    }
}

// ------------------------- launch --------------------------------------------
extern "C" void kernel_launch(void* const* d_in, const int* in_sizes, int n_in,
                              void* d_out, int out_size)
{
    const float* hidden = (const float*)d_in[0];
    const float* wq  = (const float*)d_in[1];
    const float* wv  = (const float*)d_in[2];
    const float* wo  = (const float*)d_in[3];
    const float* wg  = (const float*)d_in[4];
    const float* cqk = (const float*)d_in[5];
    const float* cqb = (const float*)d_in[6];
    const float* ckk = (const float*)d_in[7];
    const float* ckb = (const float*)d_in[8];
    const float* W1  = (const float*)d_in[9];
    const float* b1  = (const float*)d_in[10];
    const float* tns = (const float*)d_in[11];
    const float* tnb = (const float*)d_in[12];
    const float* lrk = (const float*)d_in[13];
    const float* lrb = (const float*)d_in[14];
    const float* lti = (const float*)d_in[15];
    const float* pns = (const float*)d_in[16];
    const float* pnb = (const float*)d_in[17];
    float* out = (float*)d_out;

    float *p_xqk, *p_xv, *p_gate;
    __nv_bfloat16 *p_hh, *p_hl, *p_th, *p_tl, *p_wt;
    cudaGetSymbolAddress((void**)&p_xqk,  g_xqk);
    cudaGetSymbolAddress((void**)&p_xv,   g_xv);
    cudaGetSymbolAddress((void**)&p_gate, g_gate);
    cudaGetSymbolAddress((void**)&p_hh,   g_hh);
    cudaGetSymbolAddress((void**)&p_hl,   g_hl);
    cudaGetSymbolAddress((void**)&p_th,   g_th);
    cudaGetSymbolAddress((void**)&p_tl,   g_tl);
    cudaGetSymbolAddress((void**)&p_wt,   g_wt);

    const int smem_mma = 2 * STAGEB;
    cudaFuncSetAttribute(mma_gemm_kernel, cudaFuncAttributeMaxDynamicSharedMemorySize, smem_mma);

    // 1: lr + weight cvt fused
    prep_kernel<<<2048 + 4 * 576, 256>>>(hidden, lrk, lrb, wq, wv, wg, wo);
    // 2: hidden hi/lo split
    cvt_hilo_kernel<<<(MTOT * WID / 4 + 255) / 256, 256>>>(hidden, p_hh, p_hl, MTOT * WID / 4);
    // 3: fused QVG GEMM
    {
        dim3 gg(18, MTOT / 128);
        mma_gemm_kernel<<<gg, 256, smem_mma>>>(p_hh, p_hl, p_wt, p_wt + (size_t)3 * WW,
                                               p_xqk, p_xv, p_gate);
    }
    // 4: scan (fused conv+rope) — profiled launch
    ttt_scan_kernel<<<Bsz * NH, 512>>>(W1, b1, tns, tnb, lti, cqk, cqb, ckk, ckb);
    // 5: post LN * gelu gate
    postfuse_kernel<<<MTOT, 256>>>(pns, pnb);
    // 6: output GEMM
    {
        dim3 gg(6, MTOT / 128);
        mma_gemm_kernel<<<gg, 256, smem_mma>>>(p_th, p_tl, p_wt + (size_t)6 * WW, p_wt + (size_t)7 * WW,
                                               out, out, out);
    }
}

// round 7
// speedup vs baseline: 1.1176x; 1.1176x over previous
#include <cuda_runtime.h>
#include <cuda_bf16.h>
#include <math.h>
#include <stdint.h>

#define Bsz 4
#define SEQ 4096
#define WID 768
#define NH  12
#define MBm 16
#define NBt 256           // SEQ / MBm
#define EPSV 1e-6f
#define MTOT (Bsz*SEQ)    // 16384
#define WW   (WID*WID)

// ------------------------- scratch (device globals) -------------------------
__device__ __align__(16) float g_xqk [Bsz*SEQ*WID];
__device__ __align__(16) float g_xv  [Bsz*SEQ*WID];
__device__ __align__(16) float g_gate[Bsz*SEQ*WID];
__device__ __align__(16) float g_ttt [Bsz*SEQ*WID];
__device__ __align__(16) float g_lr  [Bsz*NH*SEQ];
__device__ __align__(16) __nv_bfloat16 g_hh[Bsz*SEQ*WID];
__device__ __align__(16) __nv_bfloat16 g_hl[Bsz*SEQ*WID];
__device__ __align__(16) __nv_bfloat16 g_th[Bsz*SEQ*WID];
__device__ __align__(16) __nv_bfloat16 g_tl[Bsz*SEQ*WID];
__device__ __align__(16) __nv_bfloat16 g_wt[8*WW];

// ------------------------- helpers -------------------------
__device__ __forceinline__ uint32_t smem_u32(const void* p) {
    uint32_t a;
    asm("{ .reg .u64 t; cvta.to.shared.u64 t, %1; cvt.u32.u64 %0, t; }" : "=r"(a) : "l"(p));
    return a;
}
__device__ __forceinline__ float wred(float v) {
#pragma unroll
    for (int o = 16; o; o >>= 1) v += __shfl_xor_sync(0xffffffffu, v, o);
    return v;
}
__device__ __forceinline__ float hred(float v) {
#pragma unroll
    for (int o = 8; o; o >>= 1) v += __shfl_xor_sync(0xffffffffu, v, o);
    return v;
}
__device__ __forceinline__ unsigned long long pk2(float lo, float hi) {
    unsigned long long r;
    asm("mov.b64 %0, {%1, %2};" : "=l"(r) : "f"(lo), "f"(hi));
    return r;
}
__device__ __forceinline__ void fma2(unsigned long long& acc,
                                     unsigned long long a, unsigned long long b) {
    asm("fma.rn.f32x2 %0, %1, %2, %0;" : "+l"(acc) : "l"(a), "l"(b));
}
__device__ __forceinline__ float2 up2(unsigned long long v) {
    float lo, hi;
    asm("mov.b64 {%0, %1}, %2;" : "=f"(lo), "=f"(hi) : "l"(v));
    return make_float2(lo, hi);
}
__device__ __forceinline__ void cpa16(uint32_t saddr, const void* g) {
    asm volatile("cp.async.cg.shared.global [%0], [%1], 16;" :: "r"(saddr), "l"(g) : "memory");
}
__device__ __forceinline__ void cpa_commit() {
    asm volatile("cp.async.commit_group;" ::: "memory");
}
__device__ __forceinline__ void ldsm4(uint32_t& r0, uint32_t& r1, uint32_t& r2, uint32_t& r3, uint32_t a) {
    asm volatile("ldmatrix.sync.aligned.m8n8.x4.shared.b16 {%0,%1,%2,%3}, [%4];"
                 : "=r"(r0), "=r"(r1), "=r"(r2), "=r"(r3) : "r"(a));
}
__device__ __forceinline__ void ldsm2(uint32_t& r0, uint32_t& r1, uint32_t a) {
    asm volatile("ldmatrix.sync.aligned.m8n8.x2.shared.b16 {%0,%1}, [%2];"
                 : "=r"(r0), "=r"(r1) : "r"(a));
}
__device__ __forceinline__ void mma16816(float* c, const uint32_t* a, const uint32_t* b) {
    asm volatile("mma.sync.aligned.m16n8k16.row.col.f32.bf16.bf16.f32 "
                 "{%0,%1,%2,%3}, {%4,%5,%6,%7}, {%8,%9}, {%0,%1,%2,%3};"
                 : "+f"(c[0]), "+f"(c[1]), "+f"(c[2]), "+f"(c[3])
                 : "r"(a[0]), "r"(a[1]), "r"(a[2]), "r"(a[3]), "r"(b[0]), "r"(b[1]));
}
__device__ __forceinline__ uint32_t pkbf(float a, float b) {
    __nv_bfloat162 v(__float2bfloat16(a), __float2bfloat16(b));
    return *(uint32_t*)&v;
}

// --------- prep kernel: lr logits (blocks [0,2048)) + weight cvt (rest) -----
__global__ __launch_bounds__(256) void prep_kernel(
    const float* __restrict__ hidden, const float* __restrict__ lrk,
    const float* __restrict__ lrb,
    const float* __restrict__ w0, const float* __restrict__ w1,
    const float* __restrict__ w2, const float* __restrict__ w3)
{
    __shared__ float sk[NH * WID];
    __shared__ float tile[32][33];
    const int tid = threadIdx.x;

    if (blockIdx.x < 2048) {
        for (int i = tid; i < NH * WID; i += 256) sk[i] = lrk[i];
        __syncthreads();
        const int gw = blockIdx.x * 8 + (tid >> 5);
        const int lane = tid & 31;
        const float* hrow = hidden + (size_t)gw * WID;
        float acc[NH];
#pragma unroll
        for (int h = 0; h < NH; h++) acc[h] = 0.f;
        for (int w = lane; w < WID; w += 32) {
            float hv = hrow[w];
#pragma unroll
            for (int h = 0; h < NH; h++) acc[h] += hv * sk[h * WID + w];
        }
        const int b = gw >> 12, n = gw & (SEQ - 1);
#pragma unroll
        for (int h = 0; h < NH; h++) {
            float v = wred(acc[h]);
            if (lane == 0) {
                float x = v + lrb[h];
                g_lr[(size_t)(b * NH + h) * SEQ + n] = (1.f / (1.f + expf(-x))) * (1.f / 64.f);
            }
        }
    } else {
        const int bi = blockIdx.x - 2048;
        const int z = bi / 576;
        const int rem = bi % 576;
        const float* w = (z == 0) ? w0 : (z == 1) ? w1 : (z == 2) ? w2 : w3;
        __nv_bfloat16* th = g_wt + ((z < 3) ? (size_t)z * WW : (size_t)6 * WW);
        __nv_bfloat16* tl = g_wt + ((z < 3) ? (size_t)(3 + z) * WW : (size_t)7 * WW);
        const int bx = (rem % 24) * 32;
        const int by = (rem / 24) * 32;
        const int x = tid & 31, y = tid >> 5;
#pragma unroll
        for (int j = 0; j < 4; j++)
            tile[y + j * 8][x] = w[(size_t)(by + y + j * 8) * WID + bx + x];
        __syncthreads();
#pragma unroll
        for (int j = 0; j < 4; j++) {
            float v = tile[x][y + j * 8];
            __nv_bfloat16 hh = __float2bfloat16(v);
            size_t o = (size_t)(bx + y + j * 8) * WID + by + x;
            th[o] = hh;
            tl[o] = __float2bfloat16(v - __bfloat162float(hh));
        }
    }
}

// ------------------------- fp32 -> bf16 hi/lo split --------------------------
__global__ __launch_bounds__(256) void cvt_hilo_kernel(
    const float* __restrict__ x, __nv_bfloat16* __restrict__ hi,
    __nv_bfloat16* __restrict__ lo, int n4)
{
    int i = blockIdx.x * 256 + threadIdx.x;
    if (i >= n4) return;
    float4 v = ((const float4*)x)[i];
    __nv_bfloat16 h0 = __float2bfloat16(v.x), h1 = __float2bfloat16(v.y);
    __nv_bfloat16 h2 = __float2bfloat16(v.z), h3 = __float2bfloat16(v.w);
    __nv_bfloat16 l0 = __float2bfloat16(v.x - __bfloat162float(h0));
    __nv_bfloat16 l1 = __float2bfloat16(v.y - __bfloat162float(h1));
    __nv_bfloat16 l2 = __float2bfloat16(v.z - __bfloat162float(h2));
    __nv_bfloat16 l3 = __float2bfloat16(v.w - __bfloat162float(h3));
    __nv_bfloat162 ph0(h0, h1), ph1(h2, h3), pl0(l0, l1), pl1(l2, l3);
    ((uint2*)hi)[i] = make_uint2(*(unsigned*)&ph0, *(unsigned*)&ph1);
    ((uint2*)lo)[i] = make_uint2(*(unsigned*)&pl0, *(unsigned*)&pl1);
}

// ------------------------- bf16-split GEMM via mma.sync ----------------------
#define TSTRIDE 40
#define TILEB  (128*TSTRIDE*2)
#define STAGEB (4*TILEB)

__global__ __launch_bounds__(256) void mma_gemm_kernel(
    const __nv_bfloat16* __restrict__ Ah, const __nv_bfloat16* __restrict__ Al,
    const __nv_bfloat16* __restrict__ Bh, const __nv_bfloat16* __restrict__ Bl,
    float* __restrict__ C0, float* __restrict__ C1, float* __restrict__ C2)
{
    extern __shared__ char smem[];
    const uint32_t sb = smem_u32(smem);
    const int tid = threadIdx.x, wid = tid >> 5, lane = tid & 31;
    const int bm = blockIdx.y * 128;
    const int bn = blockIdx.x * 128;
    const int buf = blockIdx.x / 6;
    const int coloff = (blockIdx.x % 6) * 128;
    float* C = (buf == 0) ? C0 : (buf == 1) ? C1 : C2;
    const int warpM = wid & 3, warpN = wid >> 2;

    const __nv_bfloat16* srcs[4] = {
        Ah + (size_t)bm * WID, Al + (size_t)bm * WID,
        Bh + (size_t)bn * WID, Bl + (size_t)bn * WID };

    auto load_stage = [&](int st, int k0) {
#pragma unroll
        for (int t = 0; t < 4; t++) {
#pragma unroll
            for (int rep = 0; rep < 2; rep++) {
                int li = tid + rep * 256;
                int row = li >> 2, cc = li & 3;
                const void* g = srcs[t] + (size_t)row * WID + k0 + cc * 8;
                uint32_t sa = sb + st * STAGEB + t * TILEB + row * (TSTRIDE * 2) + cc * 16;
                cpa16(sa, g);
            }
        }
        cpa_commit();
    };

    float acc[2][8][4];
#pragma unroll
    for (int i = 0; i < 2; i++)
#pragma unroll
        for (int j = 0; j < 8; j++)
#pragma unroll
            for (int k = 0; k < 4; k++) acc[i][j][k] = 0.f;

    load_stage(0, 0);

    const int NK = WID / 32;
    for (int kt = 0; kt < NK; kt++) {
        if (kt + 1 < NK) load_stage((kt + 1) & 1, (kt + 1) * 32);
        if (kt + 1 < NK) asm volatile("cp.async.wait_group 1;" ::: "memory");
        else             asm volatile("cp.async.wait_group 0;" ::: "memory");
        __syncthreads();

        const uint32_t base = sb + (kt & 1) * STAGEB;
        const int lrow = lane & 15;
        const int lcol = (lane & 16) ? 8 : 0;

#pragma unroll
        for (int kk = 0; kk < 2; kk++) {
            const int kb = kk * 16;
            uint32_t ah[2][4], al[2][4], bh[8][2], bl[8][2];
#pragma unroll
            for (int mt = 0; mt < 2; mt++) {
                uint32_t off = (uint32_t)((warpM * 32 + mt * 16 + lrow) * TSTRIDE + kb + lcol) * 2;
                ldsm4(ah[mt][0], ah[mt][1], ah[mt][2], ah[mt][3], base + 0 * TILEB + off);
                ldsm4(al[mt][0], al[mt][1], al[mt][2], al[mt][3], base + 1 * TILEB + off);
            }
#pragma unroll
            for (int ng = 0; ng < 4; ng++) {
                uint32_t off = (uint32_t)((warpN * 64 + ng * 16 + lrow) * TSTRIDE + kb + lcol) * 2;
                uint32_t r0, r1, r2, r3;
                ldsm4(r0, r1, r2, r3, base + 2 * TILEB + off);
                bh[ng * 2][0] = r0; bh[ng * 2 + 1][0] = r1;
                bh[ng * 2][1] = r2; bh[ng * 2 + 1][1] = r3;
                ldsm4(r0, r1, r2, r3, base + 3 * TILEB + off);
                bl[ng * 2][0] = r0; bl[ng * 2 + 1][0] = r1;
                bl[ng * 2][1] = r2; bl[ng * 2 + 1][1] = r3;
            }
#pragma unroll
            for (int mt = 0; mt < 2; mt++)
#pragma unroll
                for (int nt = 0; nt < 8; nt++) {
                    mma16816(acc[mt][nt], ah[mt], bh[nt]);
                    mma16816(acc[mt][nt], ah[mt], bl[nt]);
                    mma16816(acc[mt][nt], al[mt], bh[nt]);
                }
        }
        __syncthreads();
    }

    const int r0 = bm + warpM * 32 + (lane >> 2);
    const int cb = coloff + warpN * 64 + 2 * (lane & 3);
#pragma unroll
    for (int mt = 0; mt < 2; mt++)
#pragma unroll
        for (int nt = 0; nt < 8; nt++) {
            int row = r0 + mt * 16, col = cb + nt * 8;
            *(float2*)(C + (size_t)row * WID + col) = make_float2(acc[mt][nt][0], acc[mt][nt][1]);
            *(float2*)(C + (size_t)(row + 8) * WID + col) = make_float2(acc[mt][nt][2], acc[mt][nt][3]);
        }
}

// ------------------------- TTT scan (256 threads, tensor-core Z GEMM) -------
// Row layout: r=tid>>4, cg=tid&15, c0=cg*4. Warp wid owns n-cols [wid*8, wid*8+8).
// W1 kept transposed [d][k]: fp32 master (stride 76) + bf16 hi/lo (stride 72).
// smem layout (floats):
//  W1T   [0, 4864)        sXQ 4864  sXK 5952  sG 7040  sZ 8128  sZQ 9216
//  b1s 10304  Cf 10368  lr 10624  lrw 10640  toki 10656   (end 10672)
//  bf16 @ +10672: W1Th 64*72, W1Tl, sKh 16*72, sKl, sQh, sQl
#define SCAN_SMEM (10672*4 + (2*64*72 + 4*16*72)*2)

__global__ __launch_bounds__(256) void ttt_scan_kernel(
    const float* __restrict__ W1in, const float* __restrict__ b1in,
    const float* __restrict__ gin,  const float* __restrict__ bbin,
    const float* __restrict__ lti,
    const float* __restrict__ cqk, const float* __restrict__ cqb,
    const float* __restrict__ ckk, const float* __restrict__ ckb)
{
    extern __shared__ float sm[];
    float* W1T = sm;                 // [64][76]
    float* sXQ = sm + 4864;          // [16][68]
    float* sXK = sm + 5952;
    float* sG  = sm + 7040;
    float* sZ  = sm + 8128;
    float* sZQ = sm + 9216;
    float* b1s = sm + 10304;
    float* Cf  = sm + 10368;
    float* lr  = sm + 10624;
    float* lrw = sm + 10640;
    float* toki= sm + 10656;
    __nv_bfloat16* W1Th = (__nv_bfloat16*)(sm + 10672);  // [64][72]
    __nv_bfloat16* W1Tl = W1Th + 64*72;
    __nv_bfloat16* sKh  = W1Tl + 64*72;                   // [16][72]
    __nv_bfloat16* sKl  = sKh + 16*72;
    __nv_bfloat16* sQh  = sKl + 16*72;
    __nv_bfloat16* sQl  = sQh + 16*72;

    const uint32_t uKh = smem_u32(sKh), uKl = smem_u32(sKl);
    const uint32_t uQh = smem_u32(sQh), uQl = smem_u32(sQl);
    const uint32_t uWh = smem_u32(W1Th), uWl = smem_u32(W1Tl);

    const int tid = threadIdx.x;
    const int bh = blockIdx.x;
    const int b = bh / NH, h = bh % NH;
    const int lane = tid & 31, wid = tid >> 5;
    const int r  = tid >> 4;
    const int cg = tid & 15;
    const int c0 = cg * 4;

    // init W1 transposed + bf16 copies
    for (int i = tid; i < 4096; i += 256) {
        int k = i >> 6, d = i & 63;
        float v = W1in[h * 4096 + i];
        W1T[d * 76 + k] = v;
        __nv_bfloat16 hi = __float2bfloat16(v);
        W1Th[d * 72 + k] = hi;
        W1Tl[d * 72 + k] = __float2bfloat16(v - __bfloat162float(hi));
    }
    if (tid < 64) b1s[tid] = b1in[h * 64 + tid];
    if (tid < 16) toki[tid] = fmaxf(1.f / (float)(tid + 1) + lti[tid], 0.f);

    const size_t gb2 = (size_t)b * SEQ * WID + h * 64 + c0;
    const float* lrp = g_lr + (size_t)bh * SEQ;

    // constants (row layout)
    float4 wq0 = *(const float4*)(cqk + 0 * WID + h * 64 + c0);
    float4 wq1 = *(const float4*)(cqk + 1 * WID + h * 64 + c0);
    float4 wq2 = *(const float4*)(cqk + 2 * WID + h * 64 + c0);
    float4 wq3 = *(const float4*)(cqk + 3 * WID + h * 64 + c0);
    float4 wk0 = *(const float4*)(ckk + 0 * WID + h * 64 + c0);
    float4 wk1 = *(const float4*)(ckk + 1 * WID + h * 64 + c0);
    float4 wk2 = *(const float4*)(ckk + 2 * WID + h * 64 + c0);
    float4 wk3 = *(const float4*)(ckk + 3 * WID + h * 64 + c0);
    float4 qb4 = *(const float4*)(cqb + h * 64 + c0);
    float4 kb4 = *(const float4*)(ckb + h * 64 + c0);
    int j0 = c0 >> 1;
    float f0 = expf(-9.210340371976184f * (float)j0 * (1.f / 32.f));
    float f1 = expf(-9.210340371976184f * (float)(j0 + 1) * (1.f / 32.f));
    const float cs0 = cosf((float)r * f0), sn0 = sinf((float)r * f0);
    const float cs1 = cosf((float)r * f1), sn1 = sinf((float)r * f1);
    const float gv0 = gin[h * 64 + c0],     gv1 = gin[h * 64 + c0 + 1];
    const float gv2 = gin[h * 64 + c0 + 2], gv3 = gin[h * 64 + c0 + 3];
    const float bv0 = bbin[h * 64 + c0],     bv1 = bbin[h * 64 + c0 + 1];
    const float bv2 = bbin[h * 64 + c0 + 2], bv3 = bbin[h * 64 + c0 + 3];

    __syncthreads();
    const float tokir  = toki[r];
    const float toki15 = toki[15];

    // prologue prefetch (tile nb=0)
    float4 x0n = make_float4(0, 0, 0, 0), x1n = x0n, x2n = x0n, x3n = x0n;
    if (r >= 3) x0n = *(const float4*)(g_xqk + gb2 + (size_t)(r - 3) * WID);
    if (r >= 2) x1n = *(const float4*)(g_xqk + gb2 + (size_t)(r - 2) * WID);
    if (r >= 1) x2n = *(const float4*)(g_xqk + gb2 + (size_t)(r - 1) * WID);
    x3n = *(const float4*)(g_xqk + gb2 + (size_t)r * WID);
    float4 v4n = *(const float4*)(g_xv + gb2 + (size_t)r * WID);
    float lrn = (tid < 16) ? lrp[tid] : 0.f;

    // W1-update mapping: d fixed, 16 k's
    const int du = tid & 63;
    const int k0u = (tid >> 6) * 16;

    for (int nb = 0; nb < NBt; nb++) {
        __syncthreads();                                   // (A)
        float4 q4c, t4c;
        {
            float4 q, k;
            q.x = qb4.x + x0n.x * wq0.x + x1n.x * wq1.x + x2n.x * wq2.x + x3n.x * wq3.x;
            q.y = qb4.y + x0n.y * wq0.y + x1n.y * wq1.y + x2n.y * wq2.y + x3n.y * wq3.y;
            q.z = qb4.z + x0n.z * wq0.z + x1n.z * wq1.z + x2n.z * wq2.z + x3n.z * wq3.z;
            q.w = qb4.w + x0n.w * wq0.w + x1n.w * wq1.w + x2n.w * wq2.w + x3n.w * wq3.w;
            k.x = kb4.x + x0n.x * wk0.x + x1n.x * wk1.x + x2n.x * wk2.x + x3n.x * wk3.x;
            k.y = kb4.y + x0n.y * wk0.y + x1n.y * wk1.y + x2n.y * wk2.y + x3n.y * wk3.y;
            k.z = kb4.z + x0n.z * wk0.z + x1n.z * wk1.z + x2n.z * wk2.z + x3n.z * wk3.z;
            k.w = kb4.w + x0n.w * wk0.w + x1n.w * wk1.w + x2n.w * wk2.w + x3n.w * wk3.w;
            float4 qr, kr;
            qr.x = q.x * cs0 - q.y * sn0; qr.y = q.x * sn0 + q.y * cs0;
            qr.z = q.z * cs1 - q.w * sn1; qr.w = q.z * sn1 + q.w * cs1;
            kr.x = k.x * cs0 - k.y * sn0; kr.y = k.x * sn0 + k.y * cs0;
            kr.z = k.z * cs1 - k.w * sn1; kr.w = k.z * sn1 + k.w * cs1;
            *(float4*)(sXQ + r * 68 + c0) = qr;
            *(float4*)(sXK + r * 68 + c0) = kr;
            // bf16 hi/lo tiles
            uint2 kh = make_uint2(pkbf(kr.x, kr.y), pkbf(kr.z, kr.w));
            *(uint2*)(sKh + r * 72 + c0) = kh;
            __nv_bfloat162 kh01 = *(__nv_bfloat162*)&kh.x, kh23 = *(__nv_bfloat162*)&kh.y;
            *(uint2*)(sKl + r * 72 + c0) = make_uint2(
                pkbf(kr.x - __bfloat162float(kh01.x), kr.y - __bfloat162float(kh01.y)),
                pkbf(kr.z - __bfloat162float(kh23.x), kr.w - __bfloat162float(kh23.y)));
            uint2 qh = make_uint2(pkbf(qr.x, qr.y), pkbf(qr.z, qr.w));
            *(uint2*)(sQh + r * 72 + c0) = qh;
            __nv_bfloat162 qh01 = *(__nv_bfloat162*)&qh.x, qh23 = *(__nv_bfloat162*)&qh.y;
            *(uint2*)(sQl + r * 72 + c0) = make_uint2(
                pkbf(qr.x - __bfloat162float(qh01.x), qr.y - __bfloat162float(qh01.y)),
                pkbf(qr.z - __bfloat162float(qh23.x), qr.w - __bfloat162float(qh23.y)));
            q4c = qr;
            t4c = make_float4(v4n.x - kr.x, v4n.y - kr.y, v4n.z - kr.z, v4n.w - kr.w);
            if (tid < 16) { lr[tid] = lrn; lrw[tid] = toki15 * lrn; }
        }
        __syncthreads();                                   // (B)

        // prefetch next tile
        if (nb + 1 < NBt) {
            const size_t rb = gb2 + (size_t)((nb + 1) * MBm + r - 3) * WID;
            x0n = *(const float4*)(g_xqk + rb);
            x1n = *(const float4*)(g_xqk + rb + WID);
            x2n = *(const float4*)(g_xqk + rb + 2 * WID);
            x3n = *(const float4*)(g_xqk + rb + 3 * WID);
            v4n = *(const float4*)(g_xv + rb + 3 * WID);
            if (tid < 16) lrn = lrp[(nb + 1) * MBm + tid];
        }

        // ---- Z GEMM via mma.sync: Z1 = XK@W1+b1, ZQ = XQ@W1+b1 ----
        {
            const int n0 = wid * 8;
            float zk[4], zq[4];
            float bA = b1s[n0 + (lane & 3) * 2], bB = b1s[n0 + (lane & 3) * 2 + 1];
            zk[0] = bA; zk[1] = bB; zk[2] = bA; zk[3] = bB;
            zq[0] = bA; zq[1] = bB; zq[2] = bA; zq[3] = bB;
            const int la = lane & 15;
#pragma unroll
            for (int ks = 0; ks < 4; ks++) {
                const int kb = ks * 16;
                uint32_t aoff = (uint32_t)(la * 72 + kb + (lane >> 4) * 8) * 2;
                uint32_t boff = (uint32_t)((n0 + (la & 7)) * 72 + kb + (la >> 3) * 8) * 2;
                uint32_t akh[4], akl[4], aqh[4], aql[4], bhf[2], blf[2];
                ldsm4(akh[0], akh[1], akh[2], akh[3], uKh + aoff);
                ldsm4(akl[0], akl[1], akl[2], akl[3], uKl + aoff);
                ldsm4(aqh[0], aqh[1], aqh[2], aqh[3], uQh + aoff);
                ldsm4(aql[0], aql[1], aql[2], aql[3], uQl + aoff);
                ldsm2(bhf[0], bhf[1], uWh + boff);
                ldsm2(blf[0], blf[1], uWl + boff);
                mma16816(zk, akh, bhf);
                mma16816(zk, akh, blf);
                mma16816(zk, akl, bhf);
                mma16816(zq, aqh, bhf);
                mma16816(zq, aqh, blf);
                mma16816(zq, aql, bhf);
            }
            const int drow = lane >> 2;
            const int dcol = n0 + (lane & 3) * 2;
            *(float2*)(sZ  + drow * 68 + dcol)       = make_float2(zk[0], zk[1]);
            *(float2*)(sZ  + (drow + 8) * 68 + dcol) = make_float2(zk[2], zk[3]);
            *(float2*)(sZQ + drow * 68 + dcol)       = make_float2(zq[0], zq[1]);
            *(float2*)(sZQ + (drow + 8) * 68 + dcol) = make_float2(zq[2], zq[3]);
        }

        // Cf[i=r][m=cg] = toki[i]*lr[m]*(XQ[i].XK[m] + 1), m<=i (fp32 tiles)
        {
            float cf = 0.f;
            if (cg <= r) {
                unsigned long long acc = 0ULL;
#pragma unroll 8
                for (int kk = 0; kk < 32; kk++) {
                    unsigned long long a = *(const unsigned long long*)(sXQ + r * 68 + 2 * kk);
                    unsigned long long bb = *(const unsigned long long*)(sXK + cg * 68 + 2 * kk);
                    fma2(acc, a, bb);
                }
                float2 p = up2(acc);
                cf = tokir * lr[cg] * (p.x + p.y + 1.f);
            }
            Cf[r * 16 + cg] = cf;
        }
        __syncthreads();                                   // (B2) sZ/sZQ/Cf ready

        // LN-fused-L2-bwd on Z1
        {
            float4 z4 = *(const float4*)(sZ + r * 68 + c0);
            float z0 = z4.x, z1 = z4.y, z2 = z4.z, z3 = z4.w;
            float s = hred(z0 + z1 + z2 + z3);
            float qq = hred(z0 * z0 + z1 * z1 + z2 * z2 + z3 * z3);
            float m = s * (1.f / 64.f);
            float rstd = rsqrtf(qq * (1.f / 64.f) - m * m + EPSV);
            float xh0 = (z0 - m) * rstd, xh1 = (z1 - m) * rstd;
            float xh2 = (z2 - m) * rstd, xh3 = (z3 - m) * rstd;
            float gx0 = (gv0 * xh0 + bv0 - t4c.x) * gv0;
            float gx1 = (gv1 * xh1 + bv1 - t4c.y) * gv1;
            float gx2 = (gv2 * xh2 + bv2 - t4c.z) * gv2;
            float gx3 = (gv3 * xh3 + bv3 - t4c.w) * gv3;
            float s1 = hred(gx0 + gx1 + gx2 + gx3);
            float s2 = hred(gx0 * xh0 + gx1 * xh1 + gx2 * xh2 + gx3 * xh3);
            float sc = rstd * (1.f / 64.f);
            float4 gr;
            gr.x = (64.f * gx0 - s1 - xh0 * s2) * sc;
            gr.y = (64.f * gx1 - s1 - xh1 * s2) * sc;
            gr.z = (64.f * gx2 - s1 - xh2 * s2) * sc;
            gr.w = (64.f * gx3 - s1 - xh3 * s2) * sc;
            *(float4*)(sG + r * 68 + c0) = gr;
        }
        __syncthreads();                                   // (C) sG ready

        // Z1_bar = ZQ - Cf@grad ; out = XQ + ln_fwd(Z1_bar)
        {
            float4 yq = *(const float4*)(sZQ + r * 68 + c0);
            unsigned long long y01 = pk2(yq.x, yq.y);
            unsigned long long y23 = pk2(yq.z, yq.w);
#pragma unroll
            for (int mm = 0; mm < 16; mm++) {
                float nc = -Cf[r * 16 + mm];
                unsigned long long pc = pk2(nc, nc);
                ulonglong2 g = *(const ulonglong2*)(sG + mm * 68 + c0);
                fma2(y01, pc, g.x); fma2(y23, pc, g.y);
            }
            float2 pA = up2(y01), pB = up2(y23);
            float y0 = pA.x, y1 = pA.y, y2 = pB.x, y3 = pB.y;
            float s = hred(y0 + y1 + y2 + y3);
            float qq = hred(y0 * y0 + y1 * y1 + y2 * y2 + y3 * y3);
            float m = s * (1.f / 64.f);
            float rstd = rsqrtf(qq * (1.f / 64.f) - m * m + EPSV);
            float4 o;
            o.x = q4c.x + gv0 * ((y0 - m) * rstd) + bv0;
            o.y = q4c.y + gv1 * ((y1 - m) * rstd) + bv1;
            o.z = q4c.z + gv2 * ((y2 - m) * rstd) + bv2;
            o.w = q4c.w + gv3 * ((y3 - m) * rstd) + bv3;
            *(float4*)(g_ttt + gb2 + (size_t)(nb * MBm + r) * WID) = o;
        }

        // W1[d][k0u..k0u+15] -= sum_m (lrw[m]*G[m][d]) * XK[m][k]; b1 -= colsum
        {
            float bs = 0.f;
            unsigned long long acc[8];
#pragma unroll
            for (int j = 0; j < 8; j++) acc[j] = 0ULL;
#pragma unroll
            for (int mm = 0; mm < 16; mm++) {
                float gd = lrw[mm] * sG[mm * 68 + du];
                bs += gd;
                unsigned long long gp = pk2(gd, gd);
                ulonglong2 xx0 = *(const ulonglong2*)(sXK + mm * 68 + k0u);
                ulonglong2 xx1 = *(const ulonglong2*)(sXK + mm * 68 + k0u + 4);
                ulonglong2 xx2 = *(const ulonglong2*)(sXK + mm * 68 + k0u + 8);
                ulonglong2 xx3 = *(const ulonglong2*)(sXK + mm * 68 + k0u + 12);
                fma2(acc[0], gp, xx0.x); fma2(acc[1], gp, xx0.y);
                fma2(acc[2], gp, xx1.x); fma2(acc[3], gp, xx1.y);
                fma2(acc[4], gp, xx2.x); fma2(acc[5], gp, xx2.y);
                fma2(acc[6], gp, xx3.x); fma2(acc[7], gp, xx3.y);
            }
            float* wr = W1T + du * 76 + k0u;
            float nw[16];
#pragma unroll
            for (int j = 0; j < 8; j++) {
                float2 p = up2(acc[j]);
                nw[2 * j]     = wr[2 * j]     - p.x;
                nw[2 * j + 1] = wr[2 * j + 1] - p.y;
            }
#pragma unroll
            for (int j = 0; j < 4; j++)
                *(float4*)(wr + 4 * j) = make_float4(nw[4*j], nw[4*j+1], nw[4*j+2], nw[4*j+3]);
            // bf16 hi/lo copies
            uint4 hi4, lo4;
            uint32_t* hp = (uint32_t*)&hi4;
            uint32_t* lp = (uint32_t*)&lo4;
#pragma unroll
            for (int j = 0; j < 8; j++) {
                uint32_t hw = pkbf(nw[2*j], nw[2*j+1]);
                __nv_bfloat162 hv = *(__nv_bfloat162*)&hw;
                hp[j & 3] = hw;
                lp[j & 3] = pkbf(nw[2*j] - __bfloat162float(hv.x),
                                 nw[2*j+1] - __bfloat162float(hv.y));
                if ((j & 3) == 3) {
                    *(uint4*)(W1Th + du * 72 + k0u + (j >> 2) * 8) = hi4;
                    *(uint4*)(W1Tl + du * 72 + k0u + (j >> 2) * 8) = lo4;
                }
            }
            if (tid < 64) b1s[du] -= bs;
        }
    }
}

// ------------------------- post: t = gelu(gate) * LN(out) -> bf16 hi/lo -----
__global__ __launch_bounds__(256) void postfuse_kernel(
    const float* __restrict__ pns, const float* __restrict__ pnb)
{
    __shared__ float ws[8], wq2[8];
    __shared__ float smu, srs;
    const int row = blockIdx.x;
    const int tid = threadIdx.x;
    const int lane = tid & 31, wid = tid >> 5;
    const float* o = g_ttt + (size_t)row * WID;
    const float* gp = g_gate + (size_t)row * WID;

    float v[3], s = 0.f, q = 0.f;
#pragma unroll
    for (int i = 0; i < 3; i++) {
        v[i] = o[tid + i * 256];
        s += v[i]; q += v[i] * v[i];
    }
    s = wred(s); q = wred(q);
    if (lane == 0) { ws[wid] = s; wq2[wid] = q; }
    __syncthreads();
    if (tid == 0) {
        float S = 0.f, Q = 0.f;
#pragma unroll
        for (int i = 0; i < 8; i++) { S += ws[i]; Q += wq2[i]; }
        float m = S * (1.f / 768.f);
        smu = m;
        srs = rsqrtf(Q * (1.f / 768.f) - m * m + EPSV);
    }
    __syncthreads();
    const float m = smu, rs = srs;
#pragma unroll
    for (int i = 0; i < 3; i++) {
        int c = tid + i * 256;
        float z = pns[c] * ((v[i] - m) * rs) + pnb[c];
        float x = gp[c];
        float gl = 0.5f * x * (1.f + tanhf(0.7978845608028654f * (x + 0.044715f * x * x * x)));
        float val = gl * z;
        __nv_bfloat16 hi = __float2bfloat16(val);
        g_th[(size_t)row * WID + c] = hi;
        g_tl[(size_t)row * WID + c] = __float2bfloat16(val - __bfloat162float(hi));
    }
}

// ------------------------- launch --------------------------------------------
extern "C" void kernel_launch(void* const* d_in, const int* in_sizes, int n_in,
                              void* d_out, int out_size)
{
    const float* hidden = (const float*)d_in[0];
    const float* wq  = (const float*)d_in[1];
    const float* wv  = (const float*)d_in[2];
    const float* wo  = (const float*)d_in[3];
    const float* wg  = (const float*)d_in[4];
    const float* cqk = (const float*)d_in[5];
    const float* cqb = (const float*)d_in[6];
    const float* ckk = (const float*)d_in[7];
    const float* ckb = (const float*)d_in[8];
    const float* W1  = (const float*)d_in[9];
    const float* b1  = (const float*)d_in[10];
    const float* tns = (const float*)d_in[11];
    const float* tnb = (const float*)d_in[12];
    const float* lrk = (const float*)d_in[13];
    const float* lrb = (const float*)d_in[14];
    const float* lti = (const float*)d_in[15];
    const float* pns = (const float*)d_in[16];
    const float* pnb = (const float*)d_in[17];
    float* out = (float*)d_out;

    float *p_xqk, *p_xv, *p_gate;
    __nv_bfloat16 *p_hh, *p_hl, *p_th, *p_tl, *p_wt;
    cudaGetSymbolAddress((void**)&p_xqk,  g_xqk);
    cudaGetSymbolAddress((void**)&p_xv,   g_xv);
    cudaGetSymbolAddress((void**)&p_gate, g_gate);
    cudaGetSymbolAddress((void**)&p_hh,   g_hh);
    cudaGetSymbolAddress((void**)&p_hl,   g_hl);
    cudaGetSymbolAddress((void**)&p_th,   g_th);
    cudaGetSymbolAddress((void**)&p_tl,   g_tl);
    cudaGetSymbolAddress((void**)&p_wt,   g_wt);

    const int smem_mma = 2 * STAGEB;
    cudaFuncSetAttribute(mma_gemm_kernel, cudaFuncAttributeMaxDynamicSharedMemorySize, smem_mma);
    cudaFuncSetAttribute(ttt_scan_kernel, cudaFuncAttributeMaxDynamicSharedMemorySize, SCAN_SMEM);

    // 1: lr + weight cvt fused
    prep_kernel<<<2048 + 4 * 576, 256>>>(hidden, lrk, lrb, wq, wv, wg, wo);
    // 2: hidden hi/lo split
    cvt_hilo_kernel<<<(MTOT * WID / 4 + 255) / 256, 256>>>(hidden, p_hh, p_hl, MTOT * WID / 4);
    // 3: fused QVG GEMM
    {
        dim3 gg(18, MTOT / 128);
        mma_gemm_kernel<<<gg, 256, smem_mma>>>(p_hh, p_hl, p_wt, p_wt + (size_t)3 * WW,
                                               p_xqk, p_xv, p_gate);
    }
    // 4: scan (fused conv+rope, tensor-core Z GEMM) — profiled launch
    ttt_scan_kernel<<<Bsz * NH, 256, SCAN_SMEM>>>(W1, b1, tns, tnb, lti, cqk, cqb, ckk, ckb);
    // 5: post LN * gelu gate
    postfuse_kernel<<<MTOT, 256>>>(pns, pnb);
    // 6: output GEMM
    {
        dim3 gg(6, MTOT / 128);
        mma_gemm_kernel<<<gg, 256, smem_mma>>>(p_th, p_tl, p_wt + (size_t)6 * WW, p_wt + (size_t)7 * WW,
                                               out, out, out);
    }
}

// round 8
// speedup vs baseline: 1.2859x; 1.1506x over previous
#include <cuda_runtime.h>
#include <cuda_bf16.h>
#include <math.h>
#include <stdint.h>

#define Bsz 4
#define SEQ 4096
#define WID 768
#define NH  12
#define MBm 16
#define NBt 256           // SEQ / MBm
#define EPSV 1e-6f
#define MTOT (Bsz*SEQ)    // 16384
#define WW   (WID*WID)

// ------------------------- scratch (device globals) -------------------------
__device__ __align__(16) float g_xqk [Bsz*SEQ*WID];
__device__ __align__(16) float g_xv  [Bsz*SEQ*WID];
__device__ __align__(16) float g_gate[Bsz*SEQ*WID];
__device__ __align__(16) float g_ttt [Bsz*SEQ*WID];
__device__ __align__(16) float g_lr  [Bsz*NH*SEQ];
__device__ __align__(16) __nv_bfloat16 g_hh[Bsz*SEQ*WID];
__device__ __align__(16) __nv_bfloat16 g_hl[Bsz*SEQ*WID];
__device__ __align__(16) __nv_bfloat16 g_th[Bsz*SEQ*WID];
__device__ __align__(16) __nv_bfloat16 g_tl[Bsz*SEQ*WID];
__device__ __align__(16) __nv_bfloat16 g_wt[8*WW];

// ------------------------- helpers -------------------------
__device__ __forceinline__ uint32_t smem_u32(const void* p) {
    uint32_t a;
    asm("{ .reg .u64 t; cvta.to.shared.u64 t, %1; cvt.u32.u64 %0, t; }" : "=r"(a) : "l"(p));
    return a;
}
__device__ __forceinline__ float wred(float v) {
#pragma unroll
    for (int o = 16; o; o >>= 1) v += __shfl_xor_sync(0xffffffffu, v, o);
    return v;
}
__device__ __forceinline__ float hred(float v) {
#pragma unroll
    for (int o = 8; o; o >>= 1) v += __shfl_xor_sync(0xffffffffu, v, o);
    return v;
}
__device__ __forceinline__ unsigned long long pk2(float lo, float hi) {
    unsigned long long r;
    asm("mov.b64 %0, {%1, %2};" : "=l"(r) : "f"(lo), "f"(hi));
    return r;
}
__device__ __forceinline__ void fma2(unsigned long long& acc,
                                     unsigned long long a, unsigned long long b) {
    asm("fma.rn.f32x2 %0, %1, %2, %0;" : "+l"(acc) : "l"(a), "l"(b));
}
__device__ __forceinline__ float2 up2(unsigned long long v) {
    float lo, hi;
    asm("mov.b64 {%0, %1}, %2;" : "=f"(lo), "=f"(hi) : "l"(v));
    return make_float2(lo, hi);
}
__device__ __forceinline__ void cpa16(uint32_t saddr, const void* g) {
    asm volatile("cp.async.cg.shared.global [%0], [%1], 16;" :: "r"(saddr), "l"(g) : "memory");
}
__device__ __forceinline__ void cpa_commit() {
    asm volatile("cp.async.commit_group;" ::: "memory");
}
__device__ __forceinline__ void ldsm4(uint32_t& r0, uint32_t& r1, uint32_t& r2, uint32_t& r3, uint32_t a) {
    asm volatile("ldmatrix.sync.aligned.m8n8.x4.shared.b16 {%0,%1,%2,%3}, [%4];"
                 : "=r"(r0), "=r"(r1), "=r"(r2), "=r"(r3) : "r"(a));
}
__device__ __forceinline__ void ldsm4t(uint32_t& r0, uint32_t& r1, uint32_t& r2, uint32_t& r3, uint32_t a) {
    asm volatile("ldmatrix.sync.aligned.m8n8.x4.trans.shared.b16 {%0,%1,%2,%3}, [%4];"
                 : "=r"(r0), "=r"(r1), "=r"(r2), "=r"(r3) : "r"(a));
}
__device__ __forceinline__ void ldsm2t(uint32_t& r0, uint32_t& r1, uint32_t a) {
    asm volatile("ldmatrix.sync.aligned.m8n8.x2.trans.shared.b16 {%0,%1}, [%2];"
                 : "=r"(r0), "=r"(r1) : "r"(a));
}
__device__ __forceinline__ void mma16816(float* c, const uint32_t* a, const uint32_t* b) {
    asm volatile("mma.sync.aligned.m16n8k16.row.col.f32.bf16.bf16.f32 "
                 "{%0,%1,%2,%3}, {%4,%5,%6,%7}, {%8,%9}, {%0,%1,%2,%3};"
                 : "+f"(c[0]), "+f"(c[1]), "+f"(c[2]), "+f"(c[3])
                 : "r"(a[0]), "r"(a[1]), "r"(a[2]), "r"(a[3]), "r"(b[0]), "r"(b[1]));
}
// pack2(lo,hi): bf16x2 with low half = bf(lo), high = bf(hi)
__device__ __forceinline__ uint32_t pack2(float lo, float hi) {
    uint32_t r;
    asm("cvt.rn.bf16x2.f32 %0, %1, %2;" : "=r"(r) : "f"(hi), "f"(lo));
    return r;
}
__device__ __forceinline__ float bflo(uint32_t p) { return __uint_as_float(p << 16); }
__device__ __forceinline__ float bfhi(uint32_t p) { return __uint_as_float(p & 0xffff0000u); }

// --------- prep kernel: lr logits (blocks [0,2048)) + weight cvt (rest) -----
__global__ __launch_bounds__(256) void prep_kernel(
    const float* __restrict__ hidden, const float* __restrict__ lrk,
    const float* __restrict__ lrb,
    const float* __restrict__ w0, const float* __restrict__ w1,
    const float* __restrict__ w2, const float* __restrict__ w3)
{
    __shared__ float sk[NH * WID];
    __shared__ float tile[32][33];
    const int tid = threadIdx.x;

    if (blockIdx.x < 2048) {
        for (int i = tid; i < NH * WID; i += 256) sk[i] = lrk[i];
        __syncthreads();
        const int gw = blockIdx.x * 8 + (tid >> 5);
        const int lane = tid & 31;
        const float* hrow = hidden + (size_t)gw * WID;
        float acc[NH];
#pragma unroll
        for (int h = 0; h < NH; h++) acc[h] = 0.f;
        for (int w = lane; w < WID; w += 32) {
            float hv = hrow[w];
#pragma unroll
            for (int h = 0; h < NH; h++) acc[h] += hv * sk[h * WID + w];
        }
        const int b = gw >> 12, n = gw & (SEQ - 1);
#pragma unroll
        for (int h = 0; h < NH; h++) {
            float v = wred(acc[h]);
            if (lane == 0) {
                float x = v + lrb[h];
                g_lr[(size_t)(b * NH + h) * SEQ + n] = (1.f / (1.f + expf(-x))) * (1.f / 64.f);
            }
        }
    } else {
        const int bi = blockIdx.x - 2048;
        const int z = bi / 576;
        const int rem = bi % 576;
        const float* w = (z == 0) ? w0 : (z == 1) ? w1 : (z == 2) ? w2 : w3;
        __nv_bfloat16* th = g_wt + ((z < 3) ? (size_t)z * WW : (size_t)6 * WW);
        __nv_bfloat16* tl = g_wt + ((z < 3) ? (size_t)(3 + z) * WW : (size_t)7 * WW);
        const int bx = (rem % 24) * 32;
        const int by = (rem / 24) * 32;
        const int x = tid & 31, y = tid >> 5;
#pragma unroll
        for (int j = 0; j < 4; j++)
            tile[y + j * 8][x] = w[(size_t)(by + y + j * 8) * WID + bx + x];
        __syncthreads();
#pragma unroll
        for (int j = 0; j < 4; j++) {
            float v = tile[x][y + j * 8];
            __nv_bfloat16 hh = __float2bfloat16(v);
            size_t o = (size_t)(bx + y + j * 8) * WID + by + x;
            th[o] = hh;
            tl[o] = __float2bfloat16(v - __bfloat162float(hh));
        }
    }
}

// ------------------------- fp32 -> bf16 hi/lo split --------------------------
__global__ __launch_bounds__(256) void cvt_hilo_kernel(
    const float* __restrict__ x, __nv_bfloat16* __restrict__ hi,
    __nv_bfloat16* __restrict__ lo, int n4)
{
    int i = blockIdx.x * 256 + threadIdx.x;
    if (i >= n4) return;
    float4 v = ((const float4*)x)[i];
    uint32_t h0 = pack2(v.x, v.y), h1 = pack2(v.z, v.w);
    uint32_t l0 = pack2(v.x - bflo(h0), v.y - bfhi(h0));
    uint32_t l1 = pack2(v.z - bflo(h1), v.w - bfhi(h1));
    ((uint2*)hi)[i] = make_uint2(h0, h1);
    ((uint2*)lo)[i] = make_uint2(l0, l1);
}

// ------------------------- bf16-split GEMM via mma.sync ----------------------
#define TSTRIDE 40
#define TILEB  (128*TSTRIDE*2)
#define STAGEB (4*TILEB)

__global__ __launch_bounds__(256) void mma_gemm_kernel(
    const __nv_bfloat16* __restrict__ Ah, const __nv_bfloat16* __restrict__ Al,
    const __nv_bfloat16* __restrict__ Bh, const __nv_bfloat16* __restrict__ Bl,
    float* __restrict__ C0, float* __restrict__ C1, float* __restrict__ C2)
{
    extern __shared__ char smem[];
    const uint32_t sb = smem_u32(smem);
    const int tid = threadIdx.x, wid = tid >> 5, lane = tid & 31;
    const int bm = blockIdx.y * 128;
    const int bn = blockIdx.x * 128;
    const int buf = blockIdx.x / 6;
    const int coloff = (blockIdx.x % 6) * 128;
    float* C = (buf == 0) ? C0 : (buf == 1) ? C1 : C2;
    const int warpM = wid & 3, warpN = wid >> 2;

    const __nv_bfloat16* srcs[4] = {
        Ah + (size_t)bm * WID, Al + (size_t)bm * WID,
        Bh + (size_t)bn * WID, Bl + (size_t)bn * WID };

    auto load_stage = [&](int st, int k0) {
#pragma unroll
        for (int t = 0; t < 4; t++) {
#pragma unroll
            for (int rep = 0; rep < 2; rep++) {
                int li = tid + rep * 256;
                int row = li >> 2, cc = li & 3;
                const void* g = srcs[t] + (size_t)row * WID + k0 + cc * 8;
                uint32_t sa = sb + st * STAGEB + t * TILEB + row * (TSTRIDE * 2) + cc * 16;
                cpa16(sa, g);
            }
        }
        cpa_commit();
    };

    float acc[2][8][4];
#pragma unroll
    for (int i = 0; i < 2; i++)
#pragma unroll
        for (int j = 0; j < 8; j++)
#pragma unroll
            for (int k = 0; k < 4; k++) acc[i][j][k] = 0.f;

    load_stage(0, 0);

    const int NK = WID / 32;
    for (int kt = 0; kt < NK; kt++) {
        if (kt + 1 < NK) load_stage((kt + 1) & 1, (kt + 1) * 32);
        if (kt + 1 < NK) asm volatile("cp.async.wait_group 1;" ::: "memory");
        else             asm volatile("cp.async.wait_group 0;" ::: "memory");
        __syncthreads();

        const uint32_t base = sb + (kt & 1) * STAGEB;
        const int lrow = lane & 15;
        const int lcol = (lane & 16) ? 8 : 0;

#pragma unroll
        for (int kk = 0; kk < 2; kk++) {
            const int kb = kk * 16;
            uint32_t ah[2][4], al[2][4], bh[8][2], bl[8][2];
#pragma unroll
            for (int mt = 0; mt < 2; mt++) {
                uint32_t off = (uint32_t)((warpM * 32 + mt * 16 + lrow) * TSTRIDE + kb + lcol) * 2;
                ldsm4(ah[mt][0], ah[mt][1], ah[mt][2], ah[mt][3], base + 0 * TILEB + off);
                ldsm4(al[mt][0], al[mt][1], al[mt][2], al[mt][3], base + 1 * TILEB + off);
            }
#pragma unroll
            for (int ng = 0; ng < 4; ng++) {
                uint32_t off = (uint32_t)((warpN * 64 + ng * 16 + lrow) * TSTRIDE + kb + lcol) * 2;
                uint32_t r0, r1, r2, r3;
                ldsm4(r0, r1, r2, r3, base + 2 * TILEB + off);
                bh[ng * 2][0] = r0; bh[ng * 2 + 1][0] = r1;
                bh[ng * 2][1] = r2; bh[ng * 2 + 1][1] = r3;
                ldsm4(r0, r1, r2, r3, base + 3 * TILEB + off);
                bl[ng * 2][0] = r0; bl[ng * 2 + 1][0] = r1;
                bl[ng * 2][1] = r2; bl[ng * 2 + 1][1] = r3;
            }
#pragma unroll
            for (int mt = 0; mt < 2; mt++)
#pragma unroll
                for (int nt = 0; nt < 8; nt++) {
                    mma16816(acc[mt][nt], ah[mt], bh[nt]);
                    mma16816(acc[mt][nt], ah[mt], bl[nt]);
                    mma16816(acc[mt][nt], al[mt], bh[nt]);
                }
        }
        __syncthreads();
    }

    const int r0 = bm + warpM * 32 + (lane >> 2);
    const int cb = coloff + warpN * 64 + 2 * (lane & 3);
#pragma unroll
    for (int mt = 0; mt < 2; mt++)
#pragma unroll
        for (int nt = 0; nt < 8; nt++) {
            int row = r0 + mt * 16, col = cb + nt * 8;
            *(float2*)(C + (size_t)row * WID + col) = make_float2(acc[mt][nt][0], acc[mt][nt][1]);
            *(float2*)(C + (size_t)(row + 8) * WID + col) = make_float2(acc[mt][nt][2], acc[mt][nt][3]);
        }
}

// ------------------------- TTT scan (256 threads) ---------------------------
// Row layout: r=tid>>4, cg=tid&15, c0=cg*4. Warp wid owns W1 n-strip [wid*8,+8).
// W1 lives ONLY in per-warp mma accumulators (fp32) + bf16 hi/lo smem [k][d].
// Z1/ZQ and the W1 update both run on mma.sync with hi/lo bf16 split.
// smem (floats): sXQ 0, sXK 1088, sG 2176, sZ 3264, sZQ 4352, b1s 5440,
//   Cf 5504, lr 5760, lrw 5776, toki 5792, end 5808.
// bf16 after: W1h[64*72], W1l, sKh[16*72], sKl, sQh, sQl, sGh, sGl.
#define SCAN_SMEM (5808*4 + (2*64*72 + 6*16*72)*2)

__global__ __launch_bounds__(256) void ttt_scan_kernel(
    const float* __restrict__ W1in, const float* __restrict__ b1in,
    const float* __restrict__ gin,  const float* __restrict__ bbin,
    const float* __restrict__ lti,
    const float* __restrict__ cqk, const float* __restrict__ cqb,
    const float* __restrict__ ckk, const float* __restrict__ ckb)
{
    extern __shared__ float sm[];
    float* sXQ = sm;                 // [16][68]
    float* sXK = sm + 1088;
    float* sG  = sm + 2176;
    float* sZ  = sm + 3264;
    float* sZQ = sm + 4352;
    float* b1s = sm + 5440;
    float* Cf  = sm + 5504;
    float* lr  = sm + 5760;
    float* lrw = sm + 5776;
    float* toki= sm + 5792;
    __nv_bfloat16* W1h = (__nv_bfloat16*)(sm + 5808);     // [64 k][72 d]
    __nv_bfloat16* W1l = W1h + 64*72;
    __nv_bfloat16* sKh = W1l + 64*72;                      // [16 m][72 k]
    __nv_bfloat16* sKl = sKh + 16*72;
    __nv_bfloat16* sQh = sKl + 16*72;
    __nv_bfloat16* sQl = sQh + 16*72;
    __nv_bfloat16* sGh = sQl + 16*72;                      // [16 m][72 d] = -lrw*grad
    __nv_bfloat16* sGl = sGh + 16*72;

    const uint32_t uKh = smem_u32(sKh), uKl = smem_u32(sKl);
    const uint32_t uQh = smem_u32(sQh), uQl = smem_u32(sQl);
    const uint32_t uWh = smem_u32(W1h), uWl = smem_u32(W1l);
    const uint32_t uGh = smem_u32(sGh), uGl = smem_u32(sGl);

    const int tid = threadIdx.x;
    const int bh = blockIdx.x;
    const int b = bh / NH, h = bh % NH;
    const int lane = tid & 31, wid = tid >> 5;
    const int r  = tid >> 4;
    const int cg = tid & 15;
    const int c0 = cg * 4;

    // init bf16 W1 [k][d]
    for (int i = tid; i < 4096; i += 256) {
        int k = i >> 6, d = i & 63;
        float v = W1in[h * 4096 + i];
        __nv_bfloat16 hi = __float2bfloat16(v);
        W1h[k * 72 + d] = hi;
        W1l[k * 72 + d] = __float2bfloat16(v - __bfloat162float(hi));
    }
    if (tid < 64) b1s[tid] = b1in[h * 64 + tid];
    if (tid < 16) toki[tid] = fmaxf(1.f / (float)(tid + 1) + lti[tid], 0.f);

    // resident W1 accumulators: warp wid owns d-cols [wid*8, wid*8+8)
    const int n0w = wid * 8;
    const int krw = lane >> 2;
    const int dcw = n0w + 2 * (lane & 3);
    float cw[4][4];
#pragma unroll
    for (int mt = 0; mt < 4; mt++) {
        const float* wsrc = W1in + h * 4096 + (mt * 16 + krw) * 64 + dcw;
        cw[mt][0] = wsrc[0];        cw[mt][1] = wsrc[1];
        cw[mt][2] = wsrc[8 * 64];   cw[mt][3] = wsrc[8 * 64 + 1];
    }

    const size_t gb2 = (size_t)b * SEQ * WID + h * 64 + c0;
    const float* lrp = g_lr + (size_t)bh * SEQ;

    // constants (row layout)
    float4 wq0 = *(const float4*)(cqk + 0 * WID + h * 64 + c0);
    float4 wq1 = *(const float4*)(cqk + 1 * WID + h * 64 + c0);
    float4 wq2 = *(const float4*)(cqk + 2 * WID + h * 64 + c0);
    float4 wq3 = *(const float4*)(cqk + 3 * WID + h * 64 + c0);
    float4 wk0 = *(const float4*)(ckk + 0 * WID + h * 64 + c0);
    float4 wk1 = *(const float4*)(ckk + 1 * WID + h * 64 + c0);
    float4 wk2 = *(const float4*)(ckk + 2 * WID + h * 64 + c0);
    float4 wk3 = *(const float4*)(ckk + 3 * WID + h * 64 + c0);
    float4 qb4 = *(const float4*)(cqb + h * 64 + c0);
    float4 kb4 = *(const float4*)(ckb + h * 64 + c0);
    int j0 = c0 >> 1;
    float f0 = expf(-9.210340371976184f * (float)j0 * (1.f / 32.f));
    float f1 = expf(-9.210340371976184f * (float)(j0 + 1) * (1.f / 32.f));
    const float cs0 = cosf((float)r * f0), sn0 = sinf((float)r * f0);
    const float cs1 = cosf((float)r * f1), sn1 = sinf((float)r * f1);
    const float gv0 = gin[h * 64 + c0],     gv1 = gin[h * 64 + c0 + 1];
    const float gv2 = gin[h * 64 + c0 + 2], gv3 = gin[h * 64 + c0 + 3];
    const float bv0 = bbin[h * 64 + c0],     bv1 = bbin[h * 64 + c0 + 1];
    const float bv2 = bbin[h * 64 + c0 + 2], bv3 = bbin[h * 64 + c0 + 3];

    __syncthreads();
    const float tokir  = toki[r];
    const float toki15 = toki[15];

    // prologue prefetch (tile nb=0)
    float4 x0n = make_float4(0, 0, 0, 0), x1n = x0n, x2n = x0n, x3n = x0n;
    if (r >= 3) x0n = *(const float4*)(g_xqk + gb2 + (size_t)(r - 3) * WID);
    if (r >= 2) x1n = *(const float4*)(g_xqk + gb2 + (size_t)(r - 2) * WID);
    if (r >= 1) x2n = *(const float4*)(g_xqk + gb2 + (size_t)(r - 1) * WID);
    x3n = *(const float4*)(g_xqk + gb2 + (size_t)r * WID);
    float4 v4n = *(const float4*)(g_xv + gb2 + (size_t)r * WID);
    float lrn = (tid < 16) ? lrp[tid] : 0.f;

    const int du = tid & 63;   // b1 update column

    for (int nb = 0; nb < NBt; nb++) {
        __syncthreads();                                   // (A)
        float4 q4c, t4c;
        {
            float4 q, k;
            q.x = qb4.x + x0n.x * wq0.x + x1n.x * wq1.x + x2n.x * wq2.x + x3n.x * wq3.x;
            q.y = qb4.y + x0n.y * wq0.y + x1n.y * wq1.y + x2n.y * wq2.y + x3n.y * wq3.y;
            q.z = qb4.z + x0n.z * wq0.z + x1n.z * wq1.z + x2n.z * wq2.z + x3n.z * wq3.z;
            q.w = qb4.w + x0n.w * wq0.w + x1n.w * wq1.w + x2n.w * wq2.w + x3n.w * wq3.w;
            k.x = kb4.x + x0n.x * wk0.x + x1n.x * wk1.x + x2n.x * wk2.x + x3n.x * wk3.x;
            k.y = kb4.y + x0n.y * wk0.y + x1n.y * wk1.y + x2n.y * wk2.y + x3n.y * wk3.y;
            k.z = kb4.z + x0n.z * wk0.z + x1n.z * wk1.z + x2n.z * wk2.z + x3n.z * wk3.z;
            k.w = kb4.w + x0n.w * wk0.w + x1n.w * wk1.w + x2n.w * wk2.w + x3n.w * wk3.w;
            float4 qr, kr;
            qr.x = q.x * cs0 - q.y * sn0; qr.y = q.x * sn0 + q.y * cs0;
            qr.z = q.z * cs1 - q.w * sn1; qr.w = q.z * sn1 + q.w * cs1;
            kr.x = k.x * cs0 - k.y * sn0; kr.y = k.x * sn0 + k.y * cs0;
            kr.z = k.z * cs1 - k.w * sn1; kr.w = k.z * sn1 + k.w * cs1;
            *(float4*)(sXQ + r * 68 + c0) = qr;
            *(float4*)(sXK + r * 68 + c0) = kr;
            uint32_t kh0 = pack2(kr.x, kr.y), kh1 = pack2(kr.z, kr.w);
            *(uint2*)(sKh + r * 72 + c0) = make_uint2(kh0, kh1);
            *(uint2*)(sKl + r * 72 + c0) = make_uint2(
                pack2(kr.x - bflo(kh0), kr.y - bfhi(kh0)),
                pack2(kr.z - bflo(kh1), kr.w - bfhi(kh1)));
            uint32_t qh0 = pack2(qr.x, qr.y), qh1 = pack2(qr.z, qr.w);
            *(uint2*)(sQh + r * 72 + c0) = make_uint2(qh0, qh1);
            *(uint2*)(sQl + r * 72 + c0) = make_uint2(
                pack2(qr.x - bflo(qh0), qr.y - bfhi(qh0)),
                pack2(qr.z - bflo(qh1), qr.w - bfhi(qh1)));
            q4c = qr;
            t4c = make_float4(v4n.x - kr.x, v4n.y - kr.y, v4n.z - kr.z, v4n.w - kr.w);
            if (tid < 16) { lr[tid] = lrn; lrw[tid] = toki15 * lrn; }
        }
        __syncthreads();                                   // (B)

        // prefetch next tile
        if (nb + 1 < NBt) {
            const size_t rb = gb2 + (size_t)((nb + 1) * MBm + r - 3) * WID;
            x0n = *(const float4*)(g_xqk + rb);
            x1n = *(const float4*)(g_xqk + rb + WID);
            x2n = *(const float4*)(g_xqk + rb + 2 * WID);
            x3n = *(const float4*)(g_xqk + rb + 3 * WID);
            v4n = *(const float4*)(g_xv + rb + 3 * WID);
            if (tid < 16) lrn = lrp[(nb + 1) * MBm + tid];
        }

        // ---- Z GEMM: Z1 = XK@W1+b1, ZQ = XQ@W1+b1 (B via trans ldsm on [k][d]) --
        {
            float zk[4], zq[4];
            float bA = b1s[dcw], bB = b1s[dcw + 1];
            zk[0] = bA; zk[1] = bB; zk[2] = bA; zk[3] = bB;
            zq[0] = bA; zq[1] = bB; zq[2] = bA; zq[3] = bB;
            const int la = lane & 15;
#pragma unroll
            for (int ks = 0; ks < 4; ks++) {
                const int kb = ks * 16;
                uint32_t aoff = (uint32_t)(la * 72 + kb + (lane >> 4) * 8) * 2;
                uint32_t boff = (uint32_t)((kb + la) * 72 + n0w) * 2;
                uint32_t akh[4], akl[4], aqh[4], aql[4], bhf[2], blf[2];
                ldsm4(akh[0], akh[1], akh[2], akh[3], uKh + aoff);
                ldsm4(akl[0], akl[1], akl[2], akl[3], uKl + aoff);
                ldsm4(aqh[0], aqh[1], aqh[2], aqh[3], uQh + aoff);
                ldsm4(aql[0], aql[1], aql[2], aql[3], uQl + aoff);
                ldsm2t(bhf[0], bhf[1], uWh + boff);
                ldsm2t(blf[0], blf[1], uWl + boff);
                mma16816(zk, akh, bhf);
                mma16816(zk, akh, blf);
                mma16816(zk, akl, bhf);
                mma16816(zq, aqh, bhf);
                mma16816(zq, aqh, blf);
                mma16816(zq, aql, bhf);
            }
            const int drow = lane >> 2;
            *(float2*)(sZ  + drow * 68 + dcw)       = make_float2(zk[0], zk[1]);
            *(float2*)(sZ  + (drow + 8) * 68 + dcw) = make_float2(zk[2], zk[3]);
            *(float2*)(sZQ + drow * 68 + dcw)       = make_float2(zq[0], zq[1]);
            *(float2*)(sZQ + (drow + 8) * 68 + dcw) = make_float2(zq[2], zq[3]);
        }

        // Cf[i=r][m=cg] = toki[i]*lr[m]*(XQ[i].XK[m] + 1), m<=i (fp32)
        {
            float cf = 0.f;
            if (cg <= r) {
                unsigned long long acc = 0ULL;
#pragma unroll 8
                for (int kk = 0; kk < 32; kk++) {
                    unsigned long long a = *(const unsigned long long*)(sXQ + r * 68 + 2 * kk);
                    unsigned long long bb = *(const unsigned long long*)(sXK + cg * 68 + 2 * kk);
                    fma2(acc, a, bb);
                }
                float2 p = up2(acc);
                cf = tokir * lr[cg] * (p.x + p.y + 1.f);
            }
            Cf[r * 16 + cg] = cf;
        }
        __syncthreads();                                   // (B2)

        // LN-fused-L2-bwd on Z1; write fp32 grad (sG) + bf16 -lrw*grad tiles
        {
            float4 z4 = *(const float4*)(sZ + r * 68 + c0);
            float z0 = z4.x, z1 = z4.y, z2 = z4.z, z3 = z4.w;
            float s = hred(z0 + z1 + z2 + z3);
            float qq = hred(z0 * z0 + z1 * z1 + z2 * z2 + z3 * z3);
            float m = s * (1.f / 64.f);
            float rstd = rsqrtf(qq * (1.f / 64.f) - m * m + EPSV);
            float xh0 = (z0 - m) * rstd, xh1 = (z1 - m) * rstd;
            float xh2 = (z2 - m) * rstd, xh3 = (z3 - m) * rstd;
            float gx0 = (gv0 * xh0 + bv0 - t4c.x) * gv0;
            float gx1 = (gv1 * xh1 + bv1 - t4c.y) * gv1;
            float gx2 = (gv2 * xh2 + bv2 - t4c.z) * gv2;
            float gx3 = (gv3 * xh3 + bv3 - t4c.w) * gv3;
            float s1 = hred(gx0 + gx1 + gx2 + gx3);
            float s2 = hred(gx0 * xh0 + gx1 * xh1 + gx2 * xh2 + gx3 * xh3);
            float sc = rstd * (1.f / 64.f);
            float4 gr;
            gr.x = (64.f * gx0 - s1 - xh0 * s2) * sc;
            gr.y = (64.f * gx1 - s1 - xh1 * s2) * sc;
            gr.z = (64.f * gx2 - s1 - xh2 * s2) * sc;
            gr.w = (64.f * gx3 - s1 - xh3 * s2) * sc;
            *(float4*)(sG + r * 68 + c0) = gr;
            float lrwr = lrw[r];
            float gw0 = -lrwr * gr.x, gw1 = -lrwr * gr.y;
            float gw2 = -lrwr * gr.z, gw3 = -lrwr * gr.w;
            uint32_t gh0 = pack2(gw0, gw1), gh1 = pack2(gw2, gw3);
            *(uint2*)(sGh + r * 72 + c0) = make_uint2(gh0, gh1);
            *(uint2*)(sGl + r * 72 + c0) = make_uint2(
                pack2(gw0 - bflo(gh0), gw1 - bfhi(gh0)),
                pack2(gw2 - bflo(gh1), gw3 - bfhi(gh1)));
        }
        __syncthreads();                                   // (C)

        // Z1_bar = ZQ - Cf@grad ; out = XQ + ln_fwd(Z1_bar)
        {
            float4 yq = *(const float4*)(sZQ + r * 68 + c0);
            unsigned long long y01 = pk2(yq.x, yq.y);
            unsigned long long y23 = pk2(yq.z, yq.w);
#pragma unroll
            for (int mm = 0; mm < 16; mm++) {
                float nc = -Cf[r * 16 + mm];
                unsigned long long pc = pk2(nc, nc);
                ulonglong2 g = *(const ulonglong2*)(sG + mm * 68 + c0);
                fma2(y01, pc, g.x); fma2(y23, pc, g.y);
            }
            float2 pA = up2(y01), pB = up2(y23);
            float y0 = pA.x, y1 = pA.y, y2 = pB.x, y3 = pB.y;
            float s = hred(y0 + y1 + y2 + y3);
            float qq = hred(y0 * y0 + y1 * y1 + y2 * y2 + y3 * y3);
            float m = s * (1.f / 64.f);
            float rstd = rsqrtf(qq * (1.f / 64.f) - m * m + EPSV);
            float4 o;
            o.x = q4c.x + gv0 * ((y0 - m) * rstd) + bv0;
            o.y = q4c.y + gv1 * ((y1 - m) * rstd) + bv1;
            o.z = q4c.z + gv2 * ((y2 - m) * rstd) + bv2;
            o.w = q4c.w + gv3 * ((y3 - m) * rstd) + bv3;
            *(float4*)(g_ttt + gb2 + (size_t)(nb * MBm + r) * WID) = o;
        }

        // W1 update on tensor cores: cw += XK^T @ (-lrw*grad)  (hi/lo split)
        {
            uint32_t bgh[2], bgl[2];
            const uint32_t gboff = (uint32_t)((lane & 15) * 72 + n0w) * 2;
            ldsm2t(bgh[0], bgh[1], uGh + gboff);
            ldsm2t(bgl[0], bgl[1], uGl + gboff);
            const int amr = ((lane >> 4) << 3) + (lane & 7);
            const int akc = ((lane >> 3) & 1) << 3;
#pragma unroll
            for (int mt = 0; mt < 4; mt++) {
                uint32_t aoff = (uint32_t)(amr * 72 + mt * 16 + akc) * 2;
                uint32_t akh[4], akl[4];
                ldsm4t(akh[0], akh[1], akh[2], akh[3], uKh + aoff);
                ldsm4t(akl[0], akl[1], akl[2], akl[3], uKl + aoff);
                mma16816(cw[mt], akh, bgh);
                mma16816(cw[mt], akh, bgl);
                mma16816(cw[mt], akl, bgh);
            }
            // writeback bf16 hi/lo copies ([k][d])
#pragma unroll
            for (int mt = 0; mt < 4; mt++) {
                int k0 = mt * 16 + krw;
                uint32_t h01 = pack2(cw[mt][0], cw[mt][1]);
                uint32_t h23 = pack2(cw[mt][2], cw[mt][3]);
                *(uint32_t*)(W1h + k0 * 72 + dcw)       = h01;
                *(uint32_t*)(W1h + (k0 + 8) * 72 + dcw) = h23;
                *(uint32_t*)(W1l + k0 * 72 + dcw) = pack2(
                    cw[mt][0] - bflo(h01), cw[mt][1] - bfhi(h01));
                *(uint32_t*)(W1l + (k0 + 8) * 72 + dcw) = pack2(
                    cw[mt][2] - bflo(h23), cw[mt][3] - bfhi(h23));
            }
            // b1 -= sum_m lrw[m]*grad[m][d]
            float bs = 0.f;
#pragma unroll
            for (int mm = 0; mm < 16; mm++) bs += lrw[mm] * sG[mm * 68 + du];
            if (tid < 64) b1s[du] -= bs;
        }
    }
}

// ------------------------- post: t = gelu(gate) * LN(out) -> bf16 hi/lo -----
__global__ __launch_bounds__(256) void postfuse_kernel(
    const float* __restrict__ pns, const float* __restrict__ pnb)
{
    __shared__ float ws[8], wq2[8];
    __shared__ float smu, srs;
    const int row = blockIdx.x;
    const int tid = threadIdx.x;
    const int lane = tid & 31, wid = tid >> 5;
    const float* o = g_ttt + (size_t)row * WID;
    const float* gp = g_gate + (size_t)row * WID;

    float v[3], s = 0.f, q = 0.f;
#pragma unroll
    for (int i = 0; i < 3; i++) {
        v[i] = o[tid + i * 256];
        s += v[i]; q += v[i] * v[i];
    }
    s = wred(s); q = wred(q);
    if (lane == 0) { ws[wid] = s; wq2[wid] = q; }
    __syncthreads();
    if (tid == 0) {
        float S = 0.f, Q = 0.f;
#pragma unroll
        for (int i = 0; i < 8; i++) { S += ws[i]; Q += wq2[i]; }
        float m = S * (1.f / 768.f);
        smu = m;
        srs = rsqrtf(Q * (1.f / 768.f) - m * m + EPSV);
    }
    __syncthreads();
    const float m = smu, rs = srs;
#pragma unroll
    for (int i = 0; i < 3; i++) {
        int c = tid + i * 256;
        float z = pns[c] * ((v[i] - m) * rs) + pnb[c];
        float x = gp[c];
        float gl = 0.5f * x * (1.f + tanhf(0.7978845608028654f * (x + 0.044715f * x * x * x)));
        float val = gl * z;
        __nv_bfloat16 hi = __float2bfloat16(val);
        g_th[(size_t)row * WID + c] = hi;
        g_tl[(size_t)row * WID + c] = __float2bfloat16(val - __bfloat162float(hi));
    }
}

// ------------------------- launch --------------------------------------------
extern "C" void kernel_launch(void* const* d_in, const int* in_sizes, int n_in,
                              void* d_out, int out_size)
{
    const float* hidden = (const float*)d_in[0];
    const float* wq  = (const float*)d_in[1];
    const float* wv  = (const float*)d_in[2];
    const float* wo  = (const float*)d_in[3];
    const float* wg  = (const float*)d_in[4];
    const float* cqk = (const float*)d_in[5];
    const float* cqb = (const float*)d_in[6];
    const float* ckk = (const float*)d_in[7];
    const float* ckb = (const float*)d_in[8];
    const float* W1  = (const float*)d_in[9];
    const float* b1  = (const float*)d_in[10];
    const float* tns = (const float*)d_in[11];
    const float* tnb = (const float*)d_in[12];
    const float* lrk = (const float*)d_in[13];
    const float* lrb = (const float*)d_in[14];
    const float* lti = (const float*)d_in[15];
    const float* pns = (const float*)d_in[16];
    const float* pnb = (const float*)d_in[17];
    float* out = (float*)d_out;

    float *p_xqk, *p_xv, *p_gate;
    __nv_bfloat16 *p_hh, *p_hl, *p_th, *p_tl, *p_wt;
    cudaGetSymbolAddress((void**)&p_xqk,  g_xqk);
    cudaGetSymbolAddress((void**)&p_xv,   g_xv);
    cudaGetSymbolAddress((void**)&p_gate, g_gate);
    cudaGetSymbolAddress((void**)&p_hh,   g_hh);
    cudaGetSymbolAddress((void**)&p_hl,   g_hl);
    cudaGetSymbolAddress((void**)&p_th,   g_th);
    cudaGetSymbolAddress((void**)&p_tl,   g_tl);
    cudaGetSymbolAddress((void**)&p_wt,   g_wt);

    const int smem_mma = 2 * STAGEB;
    cudaFuncSetAttribute(mma_gemm_kernel, cudaFuncAttributeMaxDynamicSharedMemorySize, smem_mma);
    cudaFuncSetAttribute(ttt_scan_kernel, cudaFuncAttributeMaxDynamicSharedMemorySize, SCAN_SMEM);

    // 1: lr + weight cvt fused
    prep_kernel<<<2048 + 4 * 576, 256>>>(hidden, lrk, lrb, wq, wv, wg, wo);
    // 2: hidden hi/lo split
    cvt_hilo_kernel<<<(MTOT * WID / 4 + 255) / 256, 256>>>(hidden, p_hh, p_hl, MTOT * WID / 4);
    // 3: fused QVG GEMM
    {
        dim3 gg(18, MTOT / 128);
        mma_gemm_kernel<<<gg, 256, smem_mma>>>(p_hh, p_hl, p_wt, p_wt + (size_t)3 * WW,
                                               p_xqk, p_xv, p_gate);
    }
    // 4: scan — profiled launch
    ttt_scan_kernel<<<Bsz * NH, 256, SCAN_SMEM>>>(W1, b1, tns, tnb, lti, cqk, cqb, ckk, ckb);
    // 5: post LN * gelu gate
    postfuse_kernel<<<MTOT, 256>>>(pns, pnb);
    // 6: output GEMM
    {
        dim3 gg(6, MTOT / 128);
        mma_gemm_kernel<<<gg, 256, smem_mma>>>(p_th, p_tl, p_wt + (size_t)6 * WW, p_wt + (size_t)7 * WW,
                                               out, out, out);
    }
}

// round 9
// speedup vs baseline: 1.8757x; 1.4587x over previous
#include <cuda_runtime.h>
#include <cuda_bf16.h>
#include <cuda_fp16.h>
#include <math.h>
#include <stdint.h>

#define Bsz 4
#define SEQ 4096
#define WID 768
#define NH  12
#define MBm 16
#define NBt 256           // SEQ / MBm
#define EPSV 1e-6f
#define MTOT (Bsz*SEQ)    // 16384
#define WW   (WID*WID)

// ------------------------- scratch (device globals) -------------------------
__device__ __align__(16) float g_xqk [Bsz*SEQ*WID];
__device__ __align__(16) float g_xv  [Bsz*SEQ*WID];
__device__ __align__(16) float g_gate[Bsz*SEQ*WID];
__device__ __align__(16) float g_ttt [Bsz*SEQ*WID];
__device__ __align__(16) float g_lr  [Bsz*NH*SEQ];
__device__ __align__(16) __half g_hh[Bsz*SEQ*WID];   // hidden fp16
__device__ __align__(16) __half g_th[Bsz*SEQ*WID];   // gate*z fp16
__device__ __align__(16) __half g_wt[4*WW];          // {wq,wv,wg} stacked, wo — [n][k] fp16

// ------------------------- helpers -------------------------
__device__ __forceinline__ uint32_t smem_u32(const void* p) {
    uint32_t a;
    asm("{ .reg .u64 t; cvta.to.shared.u64 t, %1; cvt.u32.u64 %0, t; }" : "=r"(a) : "l"(p));
    return a;
}
__device__ __forceinline__ float wred(float v) {
#pragma unroll
    for (int o = 16; o; o >>= 1) v += __shfl_xor_sync(0xffffffffu, v, o);
    return v;
}
__device__ __forceinline__ float hred(float v) {
#pragma unroll
    for (int o = 8; o; o >>= 1) v += __shfl_xor_sync(0xffffffffu, v, o);
    return v;
}
__device__ __forceinline__ unsigned long long pk2(float lo, float hi) {
    unsigned long long r;
    asm("mov.b64 %0, {%1, %2};" : "=l"(r) : "f"(lo), "f"(hi));
    return r;
}
__device__ __forceinline__ void fma2(unsigned long long& acc,
                                     unsigned long long a, unsigned long long b) {
    asm("fma.rn.f32x2 %0, %1, %2, %0;" : "+l"(acc) : "l"(a), "l"(b));
}
__device__ __forceinline__ float2 up2(unsigned long long v) {
    float lo, hi;
    asm("mov.b64 {%0, %1}, %2;" : "=f"(lo), "=f"(hi) : "l"(v));
    return make_float2(lo, hi);
}
__device__ __forceinline__ void cpa16(uint32_t saddr, const void* g) {
    asm volatile("cp.async.cg.shared.global [%0], [%1], 16;" :: "r"(saddr), "l"(g) : "memory");
}
__device__ __forceinline__ void cpa_commit() {
    asm volatile("cp.async.commit_group;" ::: "memory");
}
__device__ __forceinline__ void ldsm4(uint32_t& r0, uint32_t& r1, uint32_t& r2, uint32_t& r3, uint32_t a) {
    asm volatile("ldmatrix.sync.aligned.m8n8.x4.shared.b16 {%0,%1,%2,%3}, [%4];"
                 : "=r"(r0), "=r"(r1), "=r"(r2), "=r"(r3) : "r"(a));
}
__device__ __forceinline__ void ldsm4t(uint32_t& r0, uint32_t& r1, uint32_t& r2, uint32_t& r3, uint32_t a) {
    asm volatile("ldmatrix.sync.aligned.m8n8.x4.trans.shared.b16 {%0,%1,%2,%3}, [%4];"
                 : "=r"(r0), "=r"(r1), "=r"(r2), "=r"(r3) : "r"(a));
}
__device__ __forceinline__ void ldsm2t(uint32_t& r0, uint32_t& r1, uint32_t a) {
    asm volatile("ldmatrix.sync.aligned.m8n8.x2.trans.shared.b16 {%0,%1}, [%2];"
                 : "=r"(r0), "=r"(r1) : "r"(a));
}
// bf16 mma (scan)
__device__ __forceinline__ void mma16816(float* c, const uint32_t* a, const uint32_t* b) {
    asm volatile("mma.sync.aligned.m16n8k16.row.col.f32.bf16.bf16.f32 "
                 "{%0,%1,%2,%3}, {%4,%5,%6,%7}, {%8,%9}, {%0,%1,%2,%3};"
                 : "+f"(c[0]), "+f"(c[1]), "+f"(c[2]), "+f"(c[3])
                 : "r"(a[0]), "r"(a[1]), "r"(a[2]), "r"(a[3]), "r"(b[0]), "r"(b[1]));
}
// fp16 mma (big GEMMs)
__device__ __forceinline__ void mma16816h(float* c, const uint32_t* a, const uint32_t* b) {
    asm volatile("mma.sync.aligned.m16n8k16.row.col.f32.f16.f16.f32 "
                 "{%0,%1,%2,%3}, {%4,%5,%6,%7}, {%8,%9}, {%0,%1,%2,%3};"
                 : "+f"(c[0]), "+f"(c[1]), "+f"(c[2]), "+f"(c[3])
                 : "r"(a[0]), "r"(a[1]), "r"(a[2]), "r"(a[3]), "r"(b[0]), "r"(b[1]));
}
// pack2(lo,hi): bf16x2 with low half = bf(lo), high = bf(hi)
__device__ __forceinline__ uint32_t pack2(float lo, float hi) {
    uint32_t r;
    asm("cvt.rn.bf16x2.f32 %0, %1, %2;" : "=r"(r) : "f"(hi), "f"(lo));
    return r;
}
__device__ __forceinline__ float bflo(uint32_t p) { return __uint_as_float(p << 16); }
__device__ __forceinline__ float bfhi(uint32_t p) { return __uint_as_float(p & 0xffff0000u); }
__device__ __forceinline__ uint32_t packh2(float lo, float hi) {
    __half2 v(__float2half_rn(lo), __float2half_rn(hi));
    return *(uint32_t*)&v;
}

// --------- prep kernel: lr logits (blocks [0,2048)) + weight cvt (rest) -----
__global__ __launch_bounds__(256) void prep_kernel(
    const float* __restrict__ hidden, const float* __restrict__ lrk,
    const float* __restrict__ lrb,
    const float* __restrict__ w0, const float* __restrict__ w1,
    const float* __restrict__ w2, const float* __restrict__ w3)
{
    __shared__ float sk[NH * WID];
    __shared__ float tile[32][33];
    const int tid = threadIdx.x;

    if (blockIdx.x < 2048) {
        for (int i = tid; i < NH * WID; i += 256) sk[i] = lrk[i];
        __syncthreads();
        const int gw = blockIdx.x * 8 + (tid >> 5);
        const int lane = tid & 31;
        const float* hrow = hidden + (size_t)gw * WID;
        float acc[NH];
#pragma unroll
        for (int h = 0; h < NH; h++) acc[h] = 0.f;
        for (int w = lane; w < WID; w += 32) {
            float hv = hrow[w];
#pragma unroll
            for (int h = 0; h < NH; h++) acc[h] += hv * sk[h * WID + w];
        }
        const int b = gw >> 12, n = gw & (SEQ - 1);
#pragma unroll
        for (int h = 0; h < NH; h++) {
            float v = wred(acc[h]);
            if (lane == 0) {
                float x = v + lrb[h];
                g_lr[(size_t)(b * NH + h) * SEQ + n] = (1.f / (1.f + expf(-x))) * (1.f / 64.f);
            }
        }
    } else {
        const int bi = blockIdx.x - 2048;
        const int z = bi / 576;
        const int rem = bi % 576;
        const float* w = (z == 0) ? w0 : (z == 1) ? w1 : (z == 2) ? w2 : w3;
        __half* th = g_wt + (size_t)z * WW;
        const int bx = (rem % 24) * 32;
        const int by = (rem / 24) * 32;
        const int x = tid & 31, y = tid >> 5;
#pragma unroll
        for (int j = 0; j < 4; j++)
            tile[y + j * 8][x] = w[(size_t)(by + y + j * 8) * WID + bx + x];
        __syncthreads();
#pragma unroll
        for (int j = 0; j < 4; j++) {
            float v = tile[x][y + j * 8];
            th[(size_t)(bx + y + j * 8) * WID + by + x] = __float2half_rn(v);
        }
    }
}

// ------------------------- fp32 -> fp16 ---------------------------------------
__global__ __launch_bounds__(256) void cvt_h_kernel(
    const float* __restrict__ x, __half* __restrict__ hi, int n4)
{
    int i = blockIdx.x * 256 + threadIdx.x;
    if (i >= n4) return;
    float4 v = ((const float4*)x)[i];
    ((uint2*)hi)[i] = make_uint2(packh2(v.x, v.y), packh2(v.z, v.w));
}

// ------------------------- fp16 GEMM via mma.sync ----------------------------
// C[M,*] = A[M,768](fp16) @ B[n][k](fp16). 128x128 tile, BK=32, 8 warps (4Mx2N).
#define TSTRIDE 40
#define TILEB  (128*TSTRIDE*2)
#define STAGEB (2*TILEB)          // A tile + B tile

__global__ __launch_bounds__(256) void mma_gemm_kernel(
    const __half* __restrict__ Ah, const __half* __restrict__ Bh,
    float* __restrict__ C0, float* __restrict__ C1, float* __restrict__ C2)
{
    extern __shared__ char smem[];
    const uint32_t sb = smem_u32(smem);
    const int tid = threadIdx.x, wid = tid >> 5, lane = tid & 31;
    const int bm = blockIdx.y * 128;
    const int bn = blockIdx.x * 128;
    const int buf = blockIdx.x / 6;
    const int coloff = (blockIdx.x % 6) * 128;
    float* C = (buf == 0) ? C0 : (buf == 1) ? C1 : C2;
    const int warpM = wid & 3, warpN = wid >> 2;

    const __half* srcs[2] = { Ah + (size_t)bm * WID, Bh + (size_t)bn * WID };

    auto load_stage = [&](int st, int k0) {
#pragma unroll
        for (int t = 0; t < 2; t++) {
#pragma unroll
            for (int rep = 0; rep < 2; rep++) {
                int li = tid + rep * 256;
                int row = li >> 2, cc = li & 3;
                const void* g = srcs[t] + (size_t)row * WID + k0 + cc * 8;
                uint32_t sa = sb + st * STAGEB + t * TILEB + row * (TSTRIDE * 2) + cc * 16;
                cpa16(sa, g);
            }
        }
        cpa_commit();
    };

    float acc[2][8][4];
#pragma unroll
    for (int i = 0; i < 2; i++)
#pragma unroll
        for (int j = 0; j < 8; j++)
#pragma unroll
            for (int k = 0; k < 4; k++) acc[i][j][k] = 0.f;

    load_stage(0, 0);

    const int NK = WID / 32;
    for (int kt = 0; kt < NK; kt++) {
        asm volatile("cp.async.wait_group 0;" ::: "memory");
        __syncthreads();
        if (kt + 1 < NK) load_stage((kt + 1) & 1, (kt + 1) * 32);

        const uint32_t base = sb + (kt & 1) * STAGEB;
        const int lrow = lane & 15;
        const int lcol = (lane & 16) ? 8 : 0;

#pragma unroll
        for (int kk = 0; kk < 2; kk++) {
            const int kb = kk * 16;
            uint32_t ah[2][4], bhf[8][2];
#pragma unroll
            for (int mt = 0; mt < 2; mt++) {
                uint32_t off = (uint32_t)((warpM * 32 + mt * 16 + lrow) * TSTRIDE + kb + lcol) * 2;
                ldsm4(ah[mt][0], ah[mt][1], ah[mt][2], ah[mt][3], base + off);
            }
#pragma unroll
            for (int ng = 0; ng < 4; ng++) {
                uint32_t off = (uint32_t)((warpN * 64 + ng * 16 + lrow) * TSTRIDE + kb + lcol) * 2;
                uint32_t r0, r1, r2, r3;
                ldsm4(r0, r1, r2, r3, base + TILEB + off);
                bhf[ng * 2][0] = r0; bhf[ng * 2 + 1][0] = r1;
                bhf[ng * 2][1] = r2; bhf[ng * 2 + 1][1] = r3;
            }
#pragma unroll
            for (int mt = 0; mt < 2; mt++)
#pragma unroll
                for (int nt = 0; nt < 8; nt++)
                    mma16816h(acc[mt][nt], ah[mt], bhf[nt]);
        }
    }

    const int r0 = bm + warpM * 32 + (lane >> 2);
    const int cb = coloff + warpN * 64 + 2 * (lane & 3);
#pragma unroll
    for (int mt = 0; mt < 2; mt++)
#pragma unroll
        for (int nt = 0; nt < 8; nt++) {
            int row = r0 + mt * 16, col = cb + nt * 8;
            *(float2*)(C + (size_t)row * WID + col) = make_float2(acc[mt][nt][0], acc[mt][nt][1]);
            *(float2*)(C + (size_t)(row + 8) * WID + col) = make_float2(acc[mt][nt][2], acc[mt][nt][3]);
        }
}

// ------------------------- TTT scan (256 threads) — unchanged from R8 -------
#define SCAN_SMEM (5808*4 + (2*64*72 + 6*16*72)*2)

__global__ __launch_bounds__(256) void ttt_scan_kernel(
    const float* __restrict__ W1in, const float* __restrict__ b1in,
    const float* __restrict__ gin,  const float* __restrict__ bbin,
    const float* __restrict__ lti,
    const float* __restrict__ cqk, const float* __restrict__ cqb,
    const float* __restrict__ ckk, const float* __restrict__ ckb)
{
    extern __shared__ float sm[];
    float* sXQ = sm;                 // [16][68]
    float* sXK = sm + 1088;
    float* sG  = sm + 2176;
    float* sZ  = sm + 3264;
    float* sZQ = sm + 4352;
    float* b1s = sm + 5440;
    float* Cf  = sm + 5504;
    float* lr  = sm + 5760;
    float* lrw = sm + 5776;
    float* toki= sm + 5792;
    __nv_bfloat16* W1h = (__nv_bfloat16*)(sm + 5808);     // [64 k][72 d]
    __nv_bfloat16* W1l = W1h + 64*72;
    __nv_bfloat16* sKh = W1l + 64*72;                      // [16 m][72 k]
    __nv_bfloat16* sKl = sKh + 16*72;
    __nv_bfloat16* sQh = sKl + 16*72;
    __nv_bfloat16* sQl = sQh + 16*72;
    __nv_bfloat16* sGh = sQl + 16*72;                      // [16 m][72 d] = -lrw*grad
    __nv_bfloat16* sGl = sGh + 16*72;

    const uint32_t uKh = smem_u32(sKh), uKl = smem_u32(sKl);
    const uint32_t uQh = smem_u32(sQh), uQl = smem_u32(sQl);
    const uint32_t uWh = smem_u32(W1h), uWl = smem_u32(W1l);
    const uint32_t uGh = smem_u32(sGh), uGl = smem_u32(sGl);

    const int tid = threadIdx.x;
    const int bh = blockIdx.x;
    const int b = bh / NH, h = bh % NH;
    const int lane = tid & 31, wid = tid >> 5;
    const int r  = tid >> 4;
    const int cg = tid & 15;
    const int c0 = cg * 4;

    for (int i = tid; i < 4096; i += 256) {
        int k = i >> 6, d = i & 63;
        float v = W1in[h * 4096 + i];
        __nv_bfloat16 hi = __float2bfloat16(v);
        W1h[k * 72 + d] = hi;
        W1l[k * 72 + d] = __float2bfloat16(v - __bfloat162float(hi));
    }
    if (tid < 64) b1s[tid] = b1in[h * 64 + tid];
    if (tid < 16) toki[tid] = fmaxf(1.f / (float)(tid + 1) + lti[tid], 0.f);

    const int n0w = wid * 8;
    const int krw = lane >> 2;
    const int dcw = n0w + 2 * (lane & 3);
    float cw[4][4];
#pragma unroll
    for (int mt = 0; mt < 4; mt++) {
        const float* wsrc = W1in + h * 4096 + (mt * 16 + krw) * 64 + dcw;
        cw[mt][0] = wsrc[0];        cw[mt][1] = wsrc[1];
        cw[mt][2] = wsrc[8 * 64];   cw[mt][3] = wsrc[8 * 64 + 1];
    }

    const size_t gb2 = (size_t)b * SEQ * WID + h * 64 + c0;
    const float* lrp = g_lr + (size_t)bh * SEQ;

    float4 wq0 = *(const float4*)(cqk + 0 * WID + h * 64 + c0);
    float4 wq1 = *(const float4*)(cqk + 1 * WID + h * 64 + c0);
    float4 wq2 = *(const float4*)(cqk + 2 * WID + h * 64 + c0);
    float4 wq3 = *(const float4*)(cqk + 3 * WID + h * 64 + c0);
    float4 wk0 = *(const float4*)(ckk + 0 * WID + h * 64 + c0);
    float4 wk1 = *(const float4*)(ckk + 1 * WID + h * 64 + c0);
    float4 wk2 = *(const float4*)(ckk + 2 * WID + h * 64 + c0);
    float4 wk3 = *(const float4*)(ckk + 3 * WID + h * 64 + c0);
    float4 qb4 = *(const float4*)(cqb + h * 64 + c0);
    float4 kb4 = *(const float4*)(ckb + h * 64 + c0);
    int j0 = c0 >> 1;
    float f0 = expf(-9.210340371976184f * (float)j0 * (1.f / 32.f));
    float f1 = expf(-9.210340371976184f * (float)(j0 + 1) * (1.f / 32.f));
    const float cs0 = cosf((float)r * f0), sn0 = sinf((float)r * f0);
    const float cs1 = cosf((float)r * f1), sn1 = sinf((float)r * f1);
    const float gv0 = gin[h * 64 + c0],     gv1 = gin[h * 64 + c0 + 1];
    const float gv2 = gin[h * 64 + c0 + 2], gv3 = gin[h * 64 + c0 + 3];
    const float bv0 = bbin[h * 64 + c0],     bv1 = bbin[h * 64 + c0 + 1];
    const float bv2 = bbin[h * 64 + c0 + 2], bv3 = bbin[h * 64 + c0 + 3];

    __syncthreads();
    const float tokir  = toki[r];
    const float toki15 = toki[15];

    float4 x0n = make_float4(0, 0, 0, 0), x1n = x0n, x2n = x0n, x3n = x0n;
    if (r >= 3) x0n = *(const float4*)(g_xqk + gb2 + (size_t)(r - 3) * WID);
    if (r >= 2) x1n = *(const float4*)(g_xqk + gb2 + (size_t)(r - 2) * WID);
    if (r >= 1) x2n = *(const float4*)(g_xqk + gb2 + (size_t)(r - 1) * WID);
    x3n = *(const float4*)(g_xqk + gb2 + (size_t)r * WID);
    float4 v4n = *(const float4*)(g_xv + gb2 + (size_t)r * WID);
    float lrn = (tid < 16) ? lrp[tid] : 0.f;

    const int du = tid & 63;

    for (int nb = 0; nb < NBt; nb++) {
        __syncthreads();                                   // (A)
        float4 q4c, t4c;
        {
            float4 q, k;
            q.x = qb4.x + x0n.x * wq0.x + x1n.x * wq1.x + x2n.x * wq2.x + x3n.x * wq3.x;
            q.y = qb4.y + x0n.y * wq0.y + x1n.y * wq1.y + x2n.y * wq2.y + x3n.y * wq3.y;
            q.z = qb4.z + x0n.z * wq0.z + x1n.z * wq1.z + x2n.z * wq2.z + x3n.z * wq3.z;
            q.w = qb4.w + x0n.w * wq0.w + x1n.w * wq1.w + x2n.w * wq2.w + x3n.w * wq3.w;
            k.x = kb4.x + x0n.x * wk0.x + x1n.x * wk1.x + x2n.x * wk2.x + x3n.x * wk3.x;
            k.y = kb4.y + x0n.y * wk1.y * 0.f + x0n.y * wk0.y + x1n.y * wk1.y + x2n.y * wk2.y + x3n.y * wk3.y;
            k.z = kb4.z + x0n.z * wk0.z + x1n.z * wk1.z + x2n.z * wk2.z + x3n.z * wk3.z;
            k.w = kb4.w + x0n.w * wk0.w + x1n.w * wk1.w + x2n.w * wk2.w + x3n.w * wk3.w;
            float4 qr, kr;
            qr.x = q.x * cs0 - q.y * sn0; qr.y = q.x * sn0 + q.y * cs0;
            qr.z = q.z * cs1 - q.w * sn1; qr.w = q.z * sn1 + q.w * cs1;
            kr.x = k.x * cs0 - k.y * sn0; kr.y = k.x * sn0 + k.y * cs0;
            kr.z = k.z * cs1 - k.w * sn1; kr.w = k.z * sn1 + k.w * cs1;
            *(float4*)(sXQ + r * 68 + c0) = qr;
            *(float4*)(sXK + r * 68 + c0) = kr;
            uint32_t kh0 = pack2(kr.x, kr.y), kh1 = pack2(kr.z, kr.w);
            *(uint2*)(sKh + r * 72 + c0) = make_uint2(kh0, kh1);
            *(uint2*)(sKl + r * 72 + c0) = make_uint2(
                pack2(kr.x - bflo(kh0), kr.y - bfhi(kh0)),
                pack2(kr.z - bflo(kh1), kr.w - bfhi(kh1)));
            uint32_t qh0 = pack2(qr.x, qr.y), qh1 = pack2(qr.z, qr.w);
            *(uint2*)(sQh + r * 72 + c0) = make_uint2(qh0, qh1);
            *(uint2*)(sQl + r * 72 + c0) = make_uint2(
                pack2(qr.x - bflo(qh0), qr.y - bfhi(qh0)),
                pack2(qr.z - bflo(qh1), qr.w - bfhi(qh1)));
            q4c = qr;
            t4c = make_float4(v4n.x - kr.x, v4n.y - kr.y, v4n.z - kr.z, v4n.w - kr.w);
            if (tid < 16) { lr[tid] = lrn; lrw[tid] = toki15 * lrn; }
        }
        __syncthreads();                                   // (B)

        if (nb + 1 < NBt) {
            const size_t rb = gb2 + (size_t)((nb + 1) * MBm + r - 3) * WID;
            x0n = *(const float4*)(g_xqk + rb);
            x1n = *(const float4*)(g_xqk + rb + WID);
            x2n = *(const float4*)(g_xqk + rb + 2 * WID);
            x3n = *(const float4*)(g_xqk + rb + 3 * WID);
            v4n = *(const float4*)(g_xv + rb + 3 * WID);
            if (tid < 16) lrn = lrp[(nb + 1) * MBm + tid];
        }

        // Z GEMM: Z1 = XK@W1+b1, ZQ = XQ@W1+b1
        {
            float zk[4], zq[4];
            float bA = b1s[dcw], bB = b1s[dcw + 1];
            zk[0] = bA; zk[1] = bB; zk[2] = bA; zk[3] = bB;
            zq[0] = bA; zq[1] = bB; zq[2] = bA; zq[3] = bB;
            const int la = lane & 15;
#pragma unroll
            for (int ks = 0; ks < 4; ks++) {
                const int kb = ks * 16;
                uint32_t aoff = (uint32_t)(la * 72 + kb + (lane >> 4) * 8) * 2;
                uint32_t boff = (uint32_t)((kb + la) * 72 + n0w) * 2;
                uint32_t akh[4], akl[4], aqh[4], aql[4], bhf[2], blf[2];
                ldsm4(akh[0], akh[1], akh[2], akh[3], uKh + aoff);
                ldsm4(akl[0], akl[1], akl[2], akl[3], uKl + aoff);
                ldsm4(aqh[0], aqh[1], aqh[2], aqh[3], uQh + aoff);
                ldsm4(aql[0], aql[1], aql[2], aql[3], uQl + aoff);
                ldsm2t(bhf[0], bhf[1], uWh + boff);
                ldsm2t(blf[0], blf[1], uWl + boff);
                mma16816(zk, akh, bhf);
                mma16816(zk, akh, blf);
                mma16816(zk, akl, bhf);
                mma16816(zq, aqh, bhf);
                mma16816(zq, aqh, blf);
                mma16816(zq, aql, bhf);
            }
            const int drow = lane >> 2;
            *(float2*)(sZ  + drow * 68 + dcw)       = make_float2(zk[0], zk[1]);
            *(float2*)(sZ  + (drow + 8) * 68 + dcw) = make_float2(zk[2], zk[3]);
            *(float2*)(sZQ + drow * 68 + dcw)       = make_float2(zq[0], zq[1]);
            *(float2*)(sZQ + (drow + 8) * 68 + dcw) = make_float2(zq[2], zq[3]);
        }

        // Cf
        {
            float cf = 0.f;
            if (cg <= r) {
                unsigned long long acc = 0ULL;
#pragma unroll 8
                for (int kk = 0; kk < 32; kk++) {
                    unsigned long long a = *(const unsigned long long*)(sXQ + r * 68 + 2 * kk);
                    unsigned long long bb = *(const unsigned long long*)(sXK + cg * 68 + 2 * kk);
                    fma2(acc, a, bb);
                }
                float2 p = up2(acc);
                cf = tokir * lr[cg] * (p.x + p.y + 1.f);
            }
            Cf[r * 16 + cg] = cf;
        }
        __syncthreads();                                   // (B2)

        // LN-fused-L2-bwd
        {
            float4 z4 = *(const float4*)(sZ + r * 68 + c0);
            float z0 = z4.x, z1 = z4.y, z2 = z4.z, z3 = z4.w;
            float s = hred(z0 + z1 + z2 + z3);
            float qq = hred(z0 * z0 + z1 * z1 + z2 * z2 + z3 * z3);
            float m = s * (1.f / 64.f);
            float rstd = rsqrtf(qq * (1.f / 64.f) - m * m + EPSV);
            float xh0 = (z0 - m) * rstd, xh1 = (z1 - m) * rstd;
            float xh2 = (z2 - m) * rstd, xh3 = (z3 - m) * rstd;
            float gx0 = (gv0 * xh0 + bv0 - t4c.x) * gv0;
            float gx1 = (gv1 * xh1 + bv1 - t4c.y) * gv1;
            float gx2 = (gv2 * xh2 + bv2 - t4c.z) * gv2;
            float gx3 = (gv3 * xh3 + bv3 - t4c.w) * gv3;
            float s1 = hred(gx0 + gx1 + gx2 + gx3);
            float s2 = hred(gx0 * xh0 + gx1 * xh1 + gx2 * xh2 + gx3 * xh3);
            float sc = rstd * (1.f / 64.f);
            float4 gr;
            gr.x = (64.f * gx0 - s1 - xh0 * s2) * sc;
            gr.y = (64.f * gx1 - s1 - xh1 * s2) * sc;
            gr.z = (64.f * gx2 - s1 - xh2 * s2) * sc;
            gr.w = (64.f * gx3 - s1 - xh3 * s2) * sc;
            *(float4*)(sG + r * 68 + c0) = gr;
            float lrwr = lrw[r];
            float gw0 = -lrwr * gr.x, gw1 = -lrwr * gr.y;
            float gw2 = -lrwr * gr.z, gw3 = -lrwr * gr.w;
            uint32_t gh0 = pack2(gw0, gw1), gh1 = pack2(gw2, gw3);
            *(uint2*)(sGh + r * 72 + c0) = make_uint2(gh0, gh1);
            *(uint2*)(sGl + r * 72 + c0) = make_uint2(
                pack2(gw0 - bflo(gh0), gw1 - bfhi(gh0)),
                pack2(gw2 - bflo(gh1), gw3 - bfhi(gh1)));
        }
        __syncthreads();                                   // (C)

        // Z1_bar + output
        {
            float4 yq = *(const float4*)(sZQ + r * 68 + c0);
            unsigned long long y01 = pk2(yq.x, yq.y);
            unsigned long long y23 = pk2(yq.z, yq.w);
#pragma unroll
            for (int mm = 0; mm < 16; mm++) {
                float nc = -Cf[r * 16 + mm];
                unsigned long long pc = pk2(nc, nc);
                ulonglong2 g = *(const ulonglong2*)(sG + mm * 68 + c0);
                fma2(y01, pc, g.x); fma2(y23, pc, g.y);
            }
            float2 pA = up2(y01), pB = up2(y23);
            float y0 = pA.x, y1 = pA.y, y2 = pB.x, y3 = pB.y;
            float s = hred(y0 + y1 + y2 + y3);
            float qq = hred(y0 * y0 + y1 * y1 + y2 * y2 + y3 * y3);
            float m = s * (1.f / 64.f);
            float rstd = rsqrtf(qq * (1.f / 64.f) - m * m + EPSV);
            float4 o;
            o.x = q4c.x + gv0 * ((y0 - m) * rstd) + bv0;
            o.y = q4c.y + gv1 * ((y1 - m) * rstd) + bv1;
            o.z = q4c.z + gv2 * ((y2 - m) * rstd) + bv2;
            o.w = q4c.w + gv3 * ((y3 - m) * rstd) + bv3;
            *(float4*)(g_ttt + gb2 + (size_t)(nb * MBm + r) * WID) = o;
        }

        // W1 update on tensor cores
        {
            uint32_t bgh[2], bgl[2];
            const uint32_t gboff = (uint32_t)((lane & 15) * 72 + n0w) * 2;
            ldsm2t(bgh[0], bgh[1], uGh + gboff);
            ldsm2t(bgl[0], bgl[1], uGl + gboff);
            const int amr = ((lane >> 4) << 3) + (lane & 7);
            const int akc = ((lane >> 3) & 1) << 3;
#pragma unroll
            for (int mt = 0; mt < 4; mt++) {
                uint32_t aoff = (uint32_t)(amr * 72 + mt * 16 + akc) * 2;
                uint32_t akh[4], akl[4];
                ldsm4t(akh[0], akh[1], akh[2], akh[3], uKh + aoff);
                ldsm4t(akl[0], akl[1], akl[2], akl[3], uKl + aoff);
                mma16816(cw[mt], akh, bgh);
                mma16816(cw[mt], akh, bgl);
                mma16816(cw[mt], akl, bgh);
            }
#pragma unroll
            for (int mt = 0; mt < 4; mt++) {
                int k0 = mt * 16 + krw;
                uint32_t h01 = pack2(cw[mt][0], cw[mt][1]);
                uint32_t h23 = pack2(cw[mt][2], cw[mt][3]);
                *(uint32_t*)(W1h + k0 * 72 + dcw)       = h01;
                *(uint32_t*)(W1h + (k0 + 8) * 72 + dcw) = h23;
                *(uint32_t*)(W1l + k0 * 72 + dcw) = pack2(
                    cw[mt][0] - bflo(h01), cw[mt][1] - bfhi(h01));
                *(uint32_t*)(W1l + (k0 + 8) * 72 + dcw) = pack2(
                    cw[mt][2] - bflo(h23), cw[mt][3] - bfhi(h23));
            }
            float bs = 0.f;
#pragma unroll
            for (int mm = 0; mm < 16; mm++) bs += lrw[mm] * sG[mm * 68 + du];
            if (tid < 64) b1s[du] -= bs;
        }
    }
}

// ------------------------- post: t = gelu(gate) * LN(out) -> fp16 -----------
__global__ __launch_bounds__(256) void postfuse_kernel(
    const float* __restrict__ pns, const float* __restrict__ pnb)
{
    __shared__ float ws[8], wq2[8];
    __shared__ float smu, srs;
    const int row = blockIdx.x;
    const int tid = threadIdx.x;
    const int lane = tid & 31, wid = tid >> 5;
    const float* o = g_ttt + (size_t)row * WID;
    const float* gp = g_gate + (size_t)row * WID;

    float v[3], s = 0.f, q = 0.f;
#pragma unroll
    for (int i = 0; i < 3; i++) {
        v[i] = o[tid + i * 256];
        s += v[i]; q += v[i] * v[i];
    }
    s = wred(s); q = wred(q);
    if (lane == 0) { ws[wid] = s; wq2[wid] = q; }
    __syncthreads();
    if (tid == 0) {
        float S = 0.f, Q = 0.f;
#pragma unroll
        for (int i = 0; i < 8; i++) { S += ws[i]; Q += wq2[i]; }
        float m = S * (1.f / 768.f);
        smu = m;
        srs = rsqrtf(Q * (1.f / 768.f) - m * m + EPSV);
    }
    __syncthreads();
    const float m = smu, rs = srs;
#pragma unroll
    for (int i = 0; i < 3; i++) {
        int c = tid + i * 256;
        float z = pns[c] * ((v[i] - m) * rs) + pnb[c];
        float x = gp[c];
        float gl = 0.5f * x * (1.f + tanhf(0.7978845608028654f * (x + 0.044715f * x * x * x)));
        g_th[(size_t)row * WID + c] = __float2half_rn(gl * z);
    }
}

// ------------------------- launch --------------------------------------------
extern "C" void kernel_launch(void* const* d_in, const int* in_sizes, int n_in,
                              void* d_out, int out_size)
{
    const float* hidden = (const float*)d_in[0];
    const float* wq  = (const float*)d_in[1];
    const float* wv  = (const float*)d_in[2];
    const float* wo  = (const float*)d_in[3];
    const float* wg  = (const float*)d_in[4];
    const float* cqk = (const float*)d_in[5];
    const float* cqb = (const float*)d_in[6];
    const float* ckk = (const float*)d_in[7];
    const float* ckb = (const float*)d_in[8];
    const float* W1  = (const float*)d_in[9];
    const float* b1  = (const float*)d_in[10];
    const float* tns = (const float*)d_in[11];
    const float* tnb = (const float*)d_in[12];
    const float* lrk = (const float*)d_in[13];
    const float* lrb = (const float*)d_in[14];
    const float* lti = (const float*)d_in[15];
    const float* pns = (const float*)d_in[16];
    const float* pnb = (const float*)d_in[17];
    float* out = (float*)d_out;

    float *p_xqk, *p_xv, *p_gate;
    __half *p_hh, *p_th, *p_wt;
    cudaGetSymbolAddress((void**)&p_xqk,  g_xqk);
    cudaGetSymbolAddress((void**)&p_xv,   g_xv);
    cudaGetSymbolAddress((void**)&p_gate, g_gate);
    cudaGetSymbolAddress((void**)&p_hh,   g_hh);
    cudaGetSymbolAddress((void**)&p_th,   g_th);
    cudaGetSymbolAddress((void**)&p_wt,   g_wt);

    const int smem_mma = 2 * STAGEB;   // 40960
    cudaFuncSetAttribute(mma_gemm_kernel, cudaFuncAttributeMaxDynamicSharedMemorySize, smem_mma);
    cudaFuncSetAttribute(ttt_scan_kernel, cudaFuncAttributeMaxDynamicSharedMemorySize, SCAN_SMEM);

    // 1: lr + weight cvt fused
    prep_kernel<<<2048 + 4 * 576, 256>>>(hidden, lrk, lrb, wq, wv, wg, wo);
    // 2: hidden -> fp16
    cvt_h_kernel<<<(MTOT * WID / 4 + 255) / 256, 256>>>(hidden, p_hh, MTOT * WID / 4);
    // 3: fused QVG GEMM
    {
        dim3 gg(18, MTOT / 128);
        mma_gemm_kernel<<<gg, 256, smem_mma>>>(p_hh, p_wt, p_xqk, p_xv, p_gate);
    }
    // 4: scan — profiled launch
    ttt_scan_kernel<<<Bsz * NH, 256, SCAN_SMEM>>>(W1, b1, tns, tnb, lti, cqk, cqb, ckk, ckb);
    // 5: post LN * gelu gate
    postfuse_kernel<<<MTOT, 256>>>(pns, pnb);
    // 6: output GEMM
    {
        dim3 gg(6, MTOT / 128);
        mma_gemm_kernel<<<gg, 256, smem_mma>>>(p_th, p_wt + (size_t)3 * WW, out, out, out);
    }
}

// round 11
// speedup vs baseline: 2.0155x; 1.0745x over previous
#include <cuda_runtime.h>
#include <cuda_bf16.h>
#include <cuda_fp16.h>
#include <math.h>
#include <stdint.h>

#define Bsz 4
#define SEQ 4096
#define WID 768
#define NH  12
#define MBm 16
#define NBt 256           // SEQ / MBm
#define EPSV 1e-6f
#define MTOT (Bsz*SEQ)    // 16384
#define WW   (WID*WID)

// ------------------------- scratch (device globals) -------------------------
__device__ __align__(16) float g_xqk [Bsz*SEQ*WID];
__device__ __align__(16) float g_xv  [Bsz*SEQ*WID];
__device__ __align__(16) float g_gate[Bsz*SEQ*WID];
__device__ __align__(16) float g_ttt [Bsz*SEQ*WID];
__device__ __align__(16) float g_lr  [Bsz*NH*SEQ];
__device__ __align__(16) __half g_hh[Bsz*SEQ*WID];   // hidden fp16
__device__ __align__(16) __half g_th[Bsz*SEQ*WID];   // gate*z fp16
__device__ __align__(16) __half g_wt[4*WW];          // {wq,wv,wg} stacked, wo — [n][k] fp16

// ------------------------- helpers -------------------------
__device__ __forceinline__ uint32_t smem_u32(const void* p) {
    uint32_t a;
    asm("{ .reg .u64 t; cvta.to.shared.u64 t, %1; cvt.u32.u64 %0, t; }" : "=r"(a) : "l"(p));
    return a;
}
__device__ __forceinline__ float wred(float v) {
#pragma unroll
    for (int o = 16; o; o >>= 1) v += __shfl_xor_sync(0xffffffffu, v, o);
    return v;
}
__device__ __forceinline__ float hred(float v) {
#pragma unroll
    for (int o = 8; o; o >>= 1) v += __shfl_xor_sync(0xffffffffu, v, o);
    return v;
}
__device__ __forceinline__ void cpa16(uint32_t saddr, const void* g) {
    asm volatile("cp.async.cg.shared.global [%0], [%1], 16;" :: "r"(saddr), "l"(g) : "memory");
}
__device__ __forceinline__ void cpa_commit() {
    asm volatile("cp.async.commit_group;" ::: "memory");
}
__device__ __forceinline__ void ldsm4(uint32_t& r0, uint32_t& r1, uint32_t& r2, uint32_t& r3, uint32_t a) {
    asm volatile("ldmatrix.sync.aligned.m8n8.x4.shared.b16 {%0,%1,%2,%3}, [%4];"
                 : "=r"(r0), "=r"(r1), "=r"(r2), "=r"(r3) : "r"(a));
}
__device__ __forceinline__ void ldsm4t(uint32_t& r0, uint32_t& r1, uint32_t& r2, uint32_t& r3, uint32_t a) {
    asm volatile("ldmatrix.sync.aligned.m8n8.x4.trans.shared.b16 {%0,%1,%2,%3}, [%4];"
                 : "=r"(r0), "=r"(r1), "=r"(r2), "=r"(r3) : "r"(a));
}
__device__ __forceinline__ void ldsm2t(uint32_t& r0, uint32_t& r1, uint32_t a) {
    asm volatile("ldmatrix.sync.aligned.m8n8.x2.trans.shared.b16 {%0,%1}, [%2];"
                 : "=r"(r0), "=r"(r1) : "r"(a));
}
// bf16 mma (scan)
__device__ __forceinline__ void mma16816(float* c, const uint32_t* a, const uint32_t* b) {
    asm volatile("mma.sync.aligned.m16n8k16.row.col.f32.bf16.bf16.f32 "
                 "{%0,%1,%2,%3}, {%4,%5,%6,%7}, {%8,%9}, {%0,%1,%2,%3};"
                 : "+f"(c[0]), "+f"(c[1]), "+f"(c[2]), "+f"(c[3])
                 : "r"(a[0]), "r"(a[1]), "r"(a[2]), "r"(a[3]), "r"(b[0]), "r"(b[1]));
}
// fp16 mma (big GEMMs)
__device__ __forceinline__ void mma16816h(float* c, const uint32_t* a, const uint32_t* b) {
    asm volatile("mma.sync.aligned.m16n8k16.row.col.f32.f16.f16.f32 "
                 "{%0,%1,%2,%3}, {%4,%5,%6,%7}, {%8,%9}, {%0,%1,%2,%3};"
                 : "+f"(c[0]), "+f"(c[1]), "+f"(c[2]), "+f"(c[3])
                 : "r"(a[0]), "r"(a[1]), "r"(a[2]), "r"(a[3]), "r"(b[0]), "r"(b[1]));
}
// pack2(lo,hi): bf16x2 with low half = bf(lo), high = bf(hi)
__device__ __forceinline__ uint32_t pack2(float lo, float hi) {
    uint32_t r;
    asm("cvt.rn.bf16x2.f32 %0, %1, %2;" : "=r"(r) : "f"(hi), "f"(lo));
    return r;
}
__device__ __forceinline__ float bflo(uint32_t p) { return __uint_as_float(p << 16); }
__device__ __forceinline__ float bfhi(uint32_t p) { return __uint_as_float(p & 0xffff0000u); }
__device__ __forceinline__ uint32_t packh2(float lo, float hi) {
    __half2 v(__float2half_rn(lo), __float2half_rn(hi));
    return *(uint32_t*)&v;
}

// --------- prep kernel: lr logits (blocks [0,2048)) + weight cvt (rest) -----
__global__ __launch_bounds__(256) void prep_kernel(
    const float* __restrict__ hidden, const float* __restrict__ lrk,
    const float* __restrict__ lrb,
    const float* __restrict__ w0, const float* __restrict__ w1,
    const float* __restrict__ w2, const float* __restrict__ w3)
{
    __shared__ float sk[NH * WID];
    __shared__ float tile[32][33];
    const int tid = threadIdx.x;

    if (blockIdx.x < 2048) {
        for (int i = tid; i < NH * WID; i += 256) sk[i] = lrk[i];
        __syncthreads();
        const int gw = blockIdx.x * 8 + (tid >> 5);
        const int lane = tid & 31;
        const float* hrow = hidden + (size_t)gw * WID;
        float acc[NH];
#pragma unroll
        for (int h = 0; h < NH; h++) acc[h] = 0.f;
        for (int w = lane; w < WID; w += 32) {
            float hv = hrow[w];
#pragma unroll
            for (int h = 0; h < NH; h++) acc[h] += hv * sk[h * WID + w];
        }
        const int b = gw >> 12, n = gw & (SEQ - 1);
#pragma unroll
        for (int h = 0; h < NH; h++) {
            float v = wred(acc[h]);
            if (lane == 0) {
                float x = v + lrb[h];
                g_lr[(size_t)(b * NH + h) * SEQ + n] = (1.f / (1.f + expf(-x))) * (1.f / 64.f);
            }
        }
    } else {
        const int bi = blockIdx.x - 2048;
        const int z = bi / 576;
        const int rem = bi % 576;
        const float* w = (z == 0) ? w0 : (z == 1) ? w1 : (z == 2) ? w2 : w3;
        __half* th = g_wt + (size_t)z * WW;
        const int bx = (rem % 24) * 32;
        const int by = (rem / 24) * 32;
        const int x = tid & 31, y = tid >> 5;
#pragma unroll
        for (int j = 0; j < 4; j++)
            tile[y + j * 8][x] = w[(size_t)(by + y + j * 8) * WID + bx + x];
        __syncthreads();
#pragma unroll
        for (int j = 0; j < 4; j++) {
            float v = tile[x][y + j * 8];
            th[(size_t)(bx + y + j * 8) * WID + by + x] = __float2half_rn(v);
        }
    }
}

// ------------------------- fp32 -> fp16 ---------------------------------------
__global__ __launch_bounds__(256) void cvt_h_kernel(
    const float* __restrict__ x, __half* __restrict__ hi, int n4)
{
    int i = blockIdx.x * 256 + threadIdx.x;
    if (i >= n4) return;
    float4 v = ((const float4*)x)[i];
    ((uint2*)hi)[i] = make_uint2(packh2(v.x, v.y), packh2(v.z, v.w));
}

// ------------------------- fp16 GEMM via mma.sync ----------------------------
#define TSTRIDE 40
#define TILEB  (128*TSTRIDE*2)
#define STAGEB (2*TILEB)

__global__ __launch_bounds__(256) void mma_gemm_kernel(
    const __half* __restrict__ Ah, const __half* __restrict__ Bh,
    float* __restrict__ C0, float* __restrict__ C1, float* __restrict__ C2)
{
    extern __shared__ char smem[];
    const uint32_t sb = smem_u32(smem);
    const int tid = threadIdx.x, wid = tid >> 5, lane = tid & 31;
    const int bm = blockIdx.y * 128;
    const int bn = blockIdx.x * 128;
    const int buf = blockIdx.x / 6;
    const int coloff = (blockIdx.x % 6) * 128;
    float* C = (buf == 0) ? C0 : (buf == 1) ? C1 : C2;
    const int warpM = wid & 3, warpN = wid >> 2;

    const __half* srcs[2] = { Ah + (size_t)bm * WID, Bh + (size_t)bn * WID };

    auto load_stage = [&](int st, int k0) {
#pragma unroll
        for (int t = 0; t < 2; t++) {
#pragma unroll
            for (int rep = 0; rep < 2; rep++) {
                int li = tid + rep * 256;
                int row = li >> 2, cc = li & 3;
                const void* g = srcs[t] + (size_t)row * WID + k0 + cc * 8;
                uint32_t sa = sb + st * STAGEB + t * TILEB + row * (TSTRIDE * 2) + cc * 16;
                cpa16(sa, g);
            }
        }
        cpa_commit();
    };

    float acc[2][8][4];
#pragma unroll
    for (int i = 0; i < 2; i++)
#pragma unroll
        for (int j = 0; j < 8; j++)
#pragma unroll
            for (int k = 0; k < 4; k++) acc[i][j][k] = 0.f;

    load_stage(0, 0);

    const int NK = WID / 32;
    for (int kt = 0; kt < NK; kt++) {
        asm volatile("cp.async.wait_group 0;" ::: "memory");
        __syncthreads();
        if (kt + 1 < NK) load_stage((kt + 1) & 1, (kt + 1) * 32);

        const uint32_t base = sb + (kt & 1) * STAGEB;
        const int lrow = lane & 15;
        const int lcol = (lane & 16) ? 8 : 0;

#pragma unroll
        for (int kk = 0; kk < 2; kk++) {
            const int kb = kk * 16;
            uint32_t ah[2][4], bhf[8][2];
#pragma unroll
            for (int mt = 0; mt < 2; mt++) {
                uint32_t off = (uint32_t)((warpM * 32 + mt * 16 + lrow) * TSTRIDE + kb + lcol) * 2;
                ldsm4(ah[mt][0], ah[mt][1], ah[mt][2], ah[mt][3], base + off);
            }
#pragma unroll
            for (int ng = 0; ng < 4; ng++) {
                uint32_t off = (uint32_t)((warpN * 64 + ng * 16 + lrow) * TSTRIDE + kb + lcol) * 2;
                uint32_t r0, r1, r2, r3;
                ldsm4(r0, r1, r2, r3, base + TILEB + off);
                bhf[ng * 2][0] = r0; bhf[ng * 2 + 1][0] = r1;
                bhf[ng * 2][1] = r2; bhf[ng * 2 + 1][1] = r3;
            }
#pragma unroll
            for (int mt = 0; mt < 2; mt++)
#pragma unroll
                for (int nt = 0; nt < 8; nt++)
                    mma16816h(acc[mt][nt], ah[mt], bhf[nt]);
        }
    }

    const int r0 = bm + warpM * 32 + (lane >> 2);
    const int cb = coloff + warpN * 64 + 2 * (lane & 3);
#pragma unroll
    for (int mt = 0; mt < 2; mt++)
#pragma unroll
        for (int nt = 0; nt < 8; nt++) {
            int row = r0 + mt * 16, col = cb + nt * 8;
            *(float2*)(C + (size_t)row * WID + col) = make_float2(acc[mt][nt][0], acc[mt][nt][1]);
            *(float2*)(C + (size_t)(row + 8) * WID + col) = make_float2(acc[mt][nt][2], acc[mt][nt][3]);
        }
}

// ------------------------- TTT scan (256 threads, fully tensorized) ---------
// Cf_raw[i][m] = toki[i]*(Attn[i][m]+1)*mask (NO lr — lr lives in P tiles).
#define SCAN_SMEM (3376*4 + (2*4608 + 8*1152 + 2*384)*2)

__global__ __launch_bounds__(256) void ttt_scan_kernel(
    const float* __restrict__ W1in, const float* __restrict__ b1in,
    const float* __restrict__ gin,  const float* __restrict__ bbin,
    const float* __restrict__ lti,
    const float* __restrict__ cqk, const float* __restrict__ cqb,
    const float* __restrict__ ckk, const float* __restrict__ ckb)
{
    extern __shared__ float sm[];
    float* sG  = sm;                 // [16][68] fp32 grad
    float* sZ  = sm + 1088;          // [16][68] Z1
    float* sZb = sm + 2176;          // [16][68] Z1_bar
    float* b1s = sm + 3264;          // [64]
    float* lr  = sm + 3328;          // [16]
    float* lrw = sm + 3344;          // [16]
    float* toki= sm + 3360;          // [16]
    __nv_bfloat16* W1h = (__nv_bfloat16*)(sm + 3376);  // [64 k][72 d]
    __nv_bfloat16* W1l = W1h + 4608;
    __nv_bfloat16* sKh = W1l + 4608;                   // [16 m][72]
    __nv_bfloat16* sKl = sKh + 1152;
    __nv_bfloat16* sQh = sKl + 1152;
    __nv_bfloat16* sQl = sQh + 1152;
    __nv_bfloat16* sPh = sQl + 1152;                   // -lr[m]*grad
    __nv_bfloat16* sPl = sPh + 1152;
    __nv_bfloat16* sWGh= sPl + 1152;                   // -toki15*lr[m]*grad
    __nv_bfloat16* sWGl= sWGh + 1152;
    __nv_bfloat16* CfH = sWGl + 1152;                  // [16 i][24 m]
    __nv_bfloat16* CfL = CfH + 384;

    const uint32_t uKh = smem_u32(sKh), uKl = smem_u32(sKl);
    const uint32_t uQh = smem_u32(sQh), uQl = smem_u32(sQl);
    const uint32_t uWh = smem_u32(W1h), uWl = smem_u32(W1l);
    const uint32_t uPh = smem_u32(sPh), uPl = smem_u32(sPl);
    const uint32_t uGh = smem_u32(sWGh), uGl = smem_u32(sWGl);
    const uint32_t uCfH = smem_u32(CfH), uCfL = smem_u32(CfL);

    const int tid = threadIdx.x;
    const int bh = blockIdx.x;
    const int b = bh / NH, h = bh % NH;
    const int lane = tid & 31, wid = tid >> 5;
    const int r  = tid >> 4;
    const int cg = tid & 15;
    const int c0 = cg * 4;

    for (int i = tid; i < 4096; i += 256) {
        int k = i >> 6, d = i & 63;
        float v = W1in[h * 4096 + i];
        __nv_bfloat16 hi = __float2bfloat16(v);
        W1h[k * 72 + d] = hi;
        W1l[k * 72 + d] = __float2bfloat16(v - __bfloat162float(hi));
    }
    if (tid < 64) b1s[tid] = b1in[h * 64 + tid];
    if (tid < 16) toki[tid] = fmaxf(1.f / (float)(tid + 1) + lti[tid], 0.f);

    const int n0w = wid * 8;
    const int krw = lane >> 2;
    const int dcw = n0w + 2 * (lane & 3);
    const int drow = lane >> 2;
    float cw[4][4];
#pragma unroll
    for (int mt = 0; mt < 4; mt++) {
        const float* wsrc = W1in + h * 4096 + (mt * 16 + krw) * 64 + dcw;
        cw[mt][0] = wsrc[0];        cw[mt][1] = wsrc[1];
        cw[mt][2] = wsrc[8 * 64];   cw[mt][3] = wsrc[8 * 64 + 1];
    }

    const size_t gb2 = (size_t)b * SEQ * WID + h * 64 + c0;
    const float* lrp = g_lr + (size_t)bh * SEQ;

    float4 wq0 = *(const float4*)(cqk + 0 * WID + h * 64 + c0);
    float4 wq1 = *(const float4*)(cqk + 1 * WID + h * 64 + c0);
    float4 wq2 = *(const float4*)(cqk + 2 * WID + h * 64 + c0);
    float4 wq3 = *(const float4*)(cqk + 3 * WID + h * 64 + c0);
    float4 wk0 = *(const float4*)(ckk + 0 * WID + h * 64 + c0);
    float4 wk1 = *(const float4*)(ckk + 1 * WID + h * 64 + c0);
    float4 wk2 = *(const float4*)(ckk + 2 * WID + h * 64 + c0);
    float4 wk3 = *(const float4*)(ckk + 3 * WID + h * 64 + c0);
    float4 qb4 = *(const float4*)(cqb + h * 64 + c0);
    float4 kb4 = *(const float4*)(ckb + h * 64 + c0);
    int j0 = c0 >> 1;
    float f0 = expf(-9.210340371976184f * (float)j0 * (1.f / 32.f));
    float f1 = expf(-9.210340371976184f * (float)(j0 + 1) * (1.f / 32.f));
    const float cs0 = cosf((float)r * f0), sn0 = sinf((float)r * f0);
    const float cs1 = cosf((float)r * f1), sn1 = sinf((float)r * f1);
    const float gv0 = gin[h * 64 + c0],     gv1 = gin[h * 64 + c0 + 1];
    const float gv2 = gin[h * 64 + c0 + 2], gv3 = gin[h * 64 + c0 + 3];
    const float bv0 = bbin[h * 64 + c0],     bv1 = bbin[h * 64 + c0 + 1];
    const float bv2 = bbin[h * 64 + c0 + 2], bv3 = bbin[h * 64 + c0 + 3];

    __syncthreads();
    const float toki15 = toki[15];

    // prologue: prefetch tile nb=0 inputs, run conv/rope -> packed regs
    float4 x0n = make_float4(0, 0, 0, 0), x1n = x0n, x2n = x0n, x3n = x0n;
    if (r >= 3) x0n = *(const float4*)(g_xqk + gb2 + (size_t)(r - 3) * WID);
    if (r >= 2) x1n = *(const float4*)(g_xqk + gb2 + (size_t)(r - 2) * WID);
    if (r >= 1) x2n = *(const float4*)(g_xqk + gb2 + (size_t)(r - 1) * WID);
    x3n = *(const float4*)(g_xqk + gb2 + (size_t)r * WID);
    float4 v4n = *(const float4*)(g_xv + gb2 + (size_t)r * WID);
    float lrn = (tid < 16) ? lrp[tid] : 0.f;

    float4 q4c, t4c, q4prev = make_float4(0, 0, 0, 0);
    uint32_t kp0, kp1, klp0, klp1, qp0, qp1, qlp0, qlp1;
    {
        float4 q, k;
        q.x = qb4.x + x0n.x * wq0.x + x1n.x * wq1.x + x2n.x * wq2.x + x3n.x * wq3.x;
        q.y = qb4.y + x0n.y * wq0.y + x1n.y * wq1.y + x2n.y * wq2.y + x3n.y * wq3.y;
        q.z = qb4.z + x0n.z * wq0.z + x1n.z * wq1.z + x2n.z * wq2.z + x3n.z * wq3.z;
        q.w = qb4.w + x0n.w * wq0.w + x1n.w * wq1.w + x2n.w * wq2.w + x3n.w * wq3.w;
        k.x = kb4.x + x0n.x * wk0.x + x1n.x * wk1.x + x2n.x * wk2.x + x3n.x * wk3.x;
        k.y = kb4.y + x0n.y * wk0.y + x1n.y * wk1.y + x2n.y * wk2.y + x3n.y * wk3.y;
        k.z = kb4.z + x0n.z * wk0.z + x1n.z * wk1.z + x2n.z * wk2.z + x3n.z * wk3.z;
        k.w = kb4.w + x0n.w * wk0.w + x1n.w * wk1.w + x2n.w * wk2.w + x3n.w * wk3.w;
        float4 qr, kr;
        qr.x = q.x * cs0 - q.y * sn0; qr.y = q.x * sn0 + q.y * cs0;
        qr.z = q.z * cs1 - q.w * sn1; qr.w = q.z * sn1 + q.w * cs1;
        kr.x = k.x * cs0 - k.y * sn0; kr.y = k.x * sn0 + k.y * cs0;
        kr.z = k.z * cs1 - k.w * sn1; kr.w = k.z * sn1 + k.w * cs1;
        kp0 = pack2(kr.x, kr.y); kp1 = pack2(kr.z, kr.w);
        klp0 = pack2(kr.x - bflo(kp0), kr.y - bfhi(kp0));
        klp1 = pack2(kr.z - bflo(kp1), kr.w - bfhi(kp1));
        qp0 = pack2(qr.x, qr.y); qp1 = pack2(qr.z, qr.w);
        qlp0 = pack2(qr.x - bflo(qp0), qr.y - bfhi(qp0));
        qlp1 = pack2(qr.z - bflo(qp1), qr.w - bfhi(qp1));
        q4c = qr;
        t4c = make_float4(v4n.x - kr.x, v4n.y - kr.y, v4n.z - kr.z, v4n.w - kr.w);
    }

    for (int nb = 0; nb < NBt; nb++) {
        __syncthreads();                                   // (A)
        *(uint2*)(sKh + r * 72 + c0) = make_uint2(kp0, kp1);
        *(uint2*)(sKl + r * 72 + c0) = make_uint2(klp0, klp1);
        *(uint2*)(sQh + r * 72 + c0) = make_uint2(qp0, qp1);
        *(uint2*)(sQl + r * 72 + c0) = make_uint2(qlp0, qlp1);
        if (tid < 16) { lr[tid] = lrn; lrw[tid] = toki15 * lrn; }
        if (nb > 0) {
            float4 y4 = *(const float4*)(sZb + r * 68 + c0);
            float s = hred(y4.x + y4.y + y4.z + y4.w);
            float qq = hred(y4.x * y4.x + y4.y * y4.y + y4.z * y4.z + y4.w * y4.w);
            float m = s * (1.f / 64.f);
            float rstd = rsqrtf(qq * (1.f / 64.f) - m * m + EPSV);
            float4 o;
            o.x = q4prev.x + gv0 * ((y4.x - m) * rstd) + bv0;
            o.y = q4prev.y + gv1 * ((y4.y - m) * rstd) + bv1;
            o.z = q4prev.z + gv2 * ((y4.z - m) * rstd) + bv2;
            o.w = q4prev.w + gv3 * ((y4.w - m) * rstd) + bv3;
            *(float4*)(g_ttt + gb2 + (size_t)((nb - 1) * MBm + r) * WID) = o;
        }
        __syncthreads();                                   // (B)

        if (nb + 1 < NBt) {
            const size_t rb = gb2 + (size_t)((nb + 1) * MBm + r - 3) * WID;
            x0n = *(const float4*)(g_xqk + rb);
            x1n = *(const float4*)(g_xqk + rb + WID);
            x2n = *(const float4*)(g_xqk + rb + 2 * WID);
            x3n = *(const float4*)(g_xqk + rb + 3 * WID);
            v4n = *(const float4*)(g_xv + rb + 3 * WID);
            if (tid < 16) lrn = lrp[(nb + 1) * MBm + tid];
        }

        // Z GEMM: zk -> sZ ; zq stays in registers
        float zq[4];
        {
            float zk[4];
            float bA = b1s[dcw], bB = b1s[dcw + 1];
            zk[0] = bA; zk[1] = bB; zk[2] = bA; zk[3] = bB;
            zq[0] = bA; zq[1] = bB; zq[2] = bA; zq[3] = bB;
            const int la = lane & 15;
#pragma unroll
            for (int ks = 0; ks < 4; ks++) {
                const int kb = ks * 16;
                uint32_t aoff = (uint32_t)(la * 72 + kb + (lane >> 4) * 8) * 2;
                uint32_t boff = (uint32_t)((kb + la) * 72 + n0w) * 2;
                uint32_t akh[4], akl[4], aqh[4], aql[4], bhf[2], blf[2];
                ldsm4(akh[0], akh[1], akh[2], akh[3], uKh + aoff);
                ldsm4(akl[0], akl[1], akl[2], akl[3], uKl + aoff);
                ldsm4(aqh[0], aqh[1], aqh[2], aqh[3], uQh + aoff);
                ldsm4(aql[0], aql[1], aql[2], aql[3], uQl + aoff);
                ldsm2t(bhf[0], bhf[1], uWh + boff);
                ldsm2t(blf[0], blf[1], uWl + boff);
                mma16816(zk, akh, bhf);
                mma16816(zk, akh, blf);
                mma16816(zk, akl, bhf);
                mma16816(zq, aqh, bhf);
                mma16816(zq, aqh, blf);
                mma16816(zq, aql, bhf);
            }
            *(float2*)(sZ + drow * 68 + dcw)       = make_float2(zk[0], zk[1]);
            *(float2*)(sZ + (drow + 8) * 68 + dcw) = make_float2(zk[2], zk[3]);
        }

        // Attn + Cf on warps 0,1: Cf_raw = toki[i]*(Attn+1)*mask  (lr NOT here)
        if (wid < 2) {
            float at[4] = {0.f, 0.f, 0.f, 0.f};
            const int la = lane & 15;
#pragma unroll
            for (int ks = 0; ks < 4; ks++) {
                uint32_t off = (uint32_t)(la * 72 + ks * 16 + (lane >> 4) * 8) * 2;
                uint32_t qh4[4], ql4[4], kh4[4], kl4[4];
                ldsm4(qh4[0], qh4[1], qh4[2], qh4[3], uQh + off);
                ldsm4(ql4[0], ql4[1], ql4[2], ql4[3], uQl + off);
                ldsm4(kh4[0], kh4[1], kh4[2], kh4[3], uKh + off);
                ldsm4(kl4[0], kl4[1], kl4[2], kl4[3], uKl + off);
                uint32_t bhh[2] = { kh4[wid], kh4[wid + 2] };
                uint32_t bll[2] = { kl4[wid], kl4[wid + 2] };
                mma16816(at, qh4, bhh);
                mma16816(at, qh4, bll);
                mma16816(at, ql4, bhh);
            }
            const int i0 = lane >> 2;
            const int m0 = wid * 8 + 2 * (lane & 3);
            float ta = toki[i0], tb = toki[i0 + 8];
            float v00 = (m0     <= i0    ) ? ta * (at[0] + 1.f) : 0.f;
            float v01 = (m0 + 1 <= i0    ) ? ta * (at[1] + 1.f) : 0.f;
            float v10 = (m0     <= i0 + 8) ? tb * (at[2] + 1.f) : 0.f;
            float v11 = (m0 + 1 <= i0 + 8) ? tb * (at[3] + 1.f) : 0.f;
            uint32_t h0 = pack2(v00, v01), h1 = pack2(v10, v11);
            *(uint32_t*)(CfH + i0 * 24 + m0)       = h0;
            *(uint32_t*)(CfH + (i0 + 8) * 24 + m0) = h1;
            *(uint32_t*)(CfL + i0 * 24 + m0)       = pack2(v00 - bflo(h0), v01 - bfhi(h0));
            *(uint32_t*)(CfL + (i0 + 8) * 24 + m0) = pack2(v10 - bflo(h1), v11 - bfhi(h1));
        }
        __syncthreads();                                   // (B2)

        // LN-fused-L2-bwd; pack two bf16 grad tile sets
        {
            float4 z4 = *(const float4*)(sZ + r * 68 + c0);
            float z0 = z4.x, z1 = z4.y, z2 = z4.z, z3 = z4.w;
            float s = hred(z0 + z1 + z2 + z3);
            float qq = hred(z0 * z0 + z1 * z1 + z2 * z2 + z3 * z3);
            float m = s * (1.f / 64.f);
            float rstd = rsqrtf(qq * (1.f / 64.f) - m * m + EPSV);
            float xh0 = (z0 - m) * rstd, xh1 = (z1 - m) * rstd;
            float xh2 = (z2 - m) * rstd, xh3 = (z3 - m) * rstd;
            float gx0 = (gv0 * xh0 + bv0 - t4c.x) * gv0;
            float gx1 = (gv1 * xh1 + bv1 - t4c.y) * gv1;
            float gx2 = (gv2 * xh2 + bv2 - t4c.z) * gv2;
            float gx3 = (gv3 * xh3 + bv3 - t4c.w) * gv3;
            float s1 = hred(gx0 + gx1 + gx2 + gx3);
            float s2 = hred(gx0 * xh0 + gx1 * xh1 + gx2 * xh2 + gx3 * xh3);
            float sc = rstd * (1.f / 64.f);
            float4 gr;
            gr.x = (64.f * gx0 - s1 - xh0 * s2) * sc;
            gr.y = (64.f * gx1 - s1 - xh1 * s2) * sc;
            gr.z = (64.f * gx2 - s1 - xh2 * s2) * sc;
            gr.w = (64.f * gx3 - s1 - xh3 * s2) * sc;
            *(float4*)(sG + r * 68 + c0) = gr;
            float lrr = lr[r];
            float p0 = -lrr * gr.x, p1 = -lrr * gr.y, p2 = -lrr * gr.z, p3 = -lrr * gr.w;
            uint32_t ph0 = pack2(p0, p1), ph1 = pack2(p2, p3);
            *(uint2*)(sPh + r * 72 + c0) = make_uint2(ph0, ph1);
            *(uint2*)(sPl + r * 72 + c0) = make_uint2(
                pack2(p0 - bflo(ph0), p1 - bfhi(ph0)),
                pack2(p2 - bflo(ph1), p3 - bfhi(ph1)));
            float w0 = toki15 * p0, w1 = toki15 * p1, w2 = toki15 * p2, w3 = toki15 * p3;
            uint32_t wh0 = pack2(w0, w1), wh1 = pack2(w2, w3);
            *(uint2*)(sWGh + r * 72 + c0) = make_uint2(wh0, wh1);
            *(uint2*)(sWGl + r * 72 + c0) = make_uint2(
                pack2(w0 - bflo(wh0), w1 - bfhi(wh0)),
                pack2(w2 - bflo(wh1), w3 - bfhi(wh1)));
        }
        __syncthreads();                                   // (C)

        // Z1_bar = zq + Cf_raw @ (-lr*grad)   (mma, accumulate into zq frags)
        {
            uint32_t cfh4[4], cfl4[4], bp[2], bpl[2];
            uint32_t aoffc = (uint32_t)((lane & 15) * 24 + (lane >> 4) * 8) * 2;
            ldsm4(cfh4[0], cfh4[1], cfh4[2], cfh4[3], uCfH + aoffc);
            ldsm4(cfl4[0], cfl4[1], cfl4[2], cfl4[3], uCfL + aoffc);
            uint32_t boffp = (uint32_t)((lane & 15) * 72 + n0w) * 2;
            ldsm2t(bp[0], bp[1], uPh + boffp);
            ldsm2t(bpl[0], bpl[1], uPl + boffp);
            mma16816(zq, cfh4, bp);
            mma16816(zq, cfh4, bpl);
            mma16816(zq, cfl4, bp);
            *(float2*)(sZb + drow * 68 + dcw)       = make_float2(zq[0], zq[1]);
            *(float2*)(sZb + (drow + 8) * 68 + dcw) = make_float2(zq[2], zq[3]);
        }

        // W1 update: cw += XK^T @ (-toki15*lr*grad); bf16 writeback; b1 scalar
        {
            uint32_t bgh[2], bgl[2];
            const uint32_t gboff = (uint32_t)((lane & 15) * 72 + n0w) * 2;
            ldsm2t(bgh[0], bgh[1], uGh + gboff);
            ldsm2t(bgl[0], bgl[1], uGl + gboff);
            const int amr = ((lane >> 4) << 3) + (lane & 7);
            const int akc = ((lane >> 3) & 1) << 3;
#pragma unroll
            for (int mt = 0; mt < 4; mt++) {
                uint32_t aoff = (uint32_t)(amr * 72 + mt * 16 + akc) * 2;
                uint32_t akh[4], akl[4];
                ldsm4t(akh[0], akh[1], akh[2], akh[3], uKh + aoff);
                ldsm4t(akl[0], akl[1], akl[2], akl[3], uKl + aoff);
                mma16816(cw[mt], akh, bgh);
                mma16816(cw[mt], akh, bgl);
                mma16816(cw[mt], akl, bgh);
            }
#pragma unroll
            for (int mt = 0; mt < 4; mt++) {
                int k0 = mt * 16 + krw;
                uint32_t h01 = pack2(cw[mt][0], cw[mt][1]);
                uint32_t h23 = pack2(cw[mt][2], cw[mt][3]);
                *(uint32_t*)(W1h + k0 * 72 + dcw)       = h01;
                *(uint32_t*)(W1h + (k0 + 8) * 72 + dcw) = h23;
                *(uint32_t*)(W1l + k0 * 72 + dcw) = pack2(
                    cw[mt][0] - bflo(h01), cw[mt][1] - bfhi(h01));
                *(uint32_t*)(W1l + (k0 + 8) * 72 + dcw) = pack2(
                    cw[mt][2] - bflo(h23), cw[mt][3] - bfhi(h23));
            }
            const int du = tid & 63;
            float bs = 0.f;
#pragma unroll
            for (int mm = 0; mm < 16; mm++) bs += lrw[mm] * sG[mm * 68 + du];
            if (tid < 64) b1s[du] -= bs;
        }

        // conv/rope for nb+1 (registers only)
        q4prev = q4c;
        if (nb + 1 < NBt) {
            float4 q, k;
            q.x = qb4.x + x0n.x * wq0.x + x1n.x * wq1.x + x2n.x * wq2.x + x3n.x * wq3.x;
            q.y = qb4.y + x0n.y * wq0.y + x1n.y * wq1.y + x2n.y * wq2.y + x3n.y * wq3.y;
            q.z = qb4.z + x0n.z * wq0.z + x1n.z * wq1.z + x2n.z * wq2.z + x3n.z * wq3.z;
            q.w = qb4.w + x0n.w * wq0.w + x1n.w * wq1.w + x2n.w * wq2.w + x3n.w * wq3.w;
            k.x = kb4.x + x0n.x * wk0.x + x1n.x * wk1.x + x2n.x * wk2.x + x3n.x * wk3.x;
            k.y = kb4.y + x0n.y * wk0.y + x1n.y * wk1.y + x2n.y * wk2.y + x3n.y * wk3.y;
            k.z = kb4.z + x0n.z * wk0.z + x1n.z * wk1.z + x2n.z * wk2.z + x3n.z * wk3.z;
            k.w = kb4.w + x0n.w * wk0.w + x1n.w * wk1.w + x2n.w * wk2.w + x3n.w * wk3.w;
            float4 qr, kr;
            qr.x = q.x * cs0 - q.y * sn0; qr.y = q.x * sn0 + q.y * cs0;
            qr.z = q.z * cs1 - q.w * sn1; qr.w = q.z * sn1 + q.w * cs1;
            kr.x = k.x * cs0 - k.y * sn0; kr.y = k.x * sn0 + k.y * cs0;
            kr.z = k.z * cs1 - k.w * sn1; kr.w = k.z * sn1 + k.w * cs1;
            kp0 = pack2(kr.x, kr.y); kp1 = pack2(kr.z, kr.w);
            klp0 = pack2(kr.x - bflo(kp0), kr.y - bfhi(kp0));
            klp1 = pack2(kr.z - bflo(kp1), kr.w - bfhi(kp1));
            qp0 = pack2(qr.x, qr.y); qp1 = pack2(qr.z, qr.w);
            qlp0 = pack2(qr.x - bflo(qp0), qr.y - bfhi(qp0));
            qlp1 = pack2(qr.z - bflo(qp1), qr.w - bfhi(qp1));
            q4c = qr;
            t4c = make_float4(v4n.x - kr.x, v4n.y - kr.y, v4n.z - kr.z, v4n.w - kr.w);
        }
    }

    // final output (nb = NBt-1)
    __syncthreads();
    {
        float4 y4 = *(const float4*)(sZb + r * 68 + c0);
        float s = hred(y4.x + y4.y + y4.z + y4.w);
        float qq = hred(y4.x * y4.x + y4.y * y4.y + y4.z * y4.z + y4.w * y4.w);
        float m = s * (1.f / 64.f);
        float rstd = rsqrtf(qq * (1.f / 64.f) - m * m + EPSV);
        float4 o;
        o.x = q4prev.x + gv0 * ((y4.x - m) * rstd) + bv0;
        o.y = q4prev.y + gv1 * ((y4.y - m) * rstd) + bv1;
        o.z = q4prev.z + gv2 * ((y4.z - m) * rstd) + bv2;
        o.w = q4prev.w + gv3 * ((y4.w - m) * rstd) + bv3;
        *(float4*)(g_ttt + gb2 + (size_t)((NBt - 1) * MBm + r) * WID) = o;
    }
}

// ------------------------- post: t = gelu(gate) * LN(out) -> fp16 -----------
__global__ __launch_bounds__(256) void postfuse_kernel(
    const float* __restrict__ pns, const float* __restrict__ pnb)
{
    __shared__ float ws[8], wq2[8];
    __shared__ float smu, srs;
    const int row = blockIdx.x;
    const int tid = threadIdx.x;
    const int lane = tid & 31, wid = tid >> 5;
    const float* o = g_ttt + (size_t)row * WID;
    const float* gp = g_gate + (size_t)row * WID;

    float v[3], s = 0.f, q = 0.f;
#pragma unroll
    for (int i = 0; i < 3; i++) {
        v[i] = o[tid + i * 256];
        s += v[i]; q += v[i] * v[i];
    }
    s = wred(s); q = wred(q);
    if (lane == 0) { ws[wid] = s; wq2[wid] = q; }
    __syncthreads();
    if (tid == 0) {
        float S = 0.f, Q = 0.f;
#pragma unroll
        for (int i = 0; i < 8; i++) { S += ws[i]; Q += wq2[i]; }
        float m = S * (1.f / 768.f);
        smu = m;
        srs = rsqrtf(Q * (1.f / 768.f) - m * m + EPSV);
    }
    __syncthreads();
    const float m = smu, rs = srs;
#pragma unroll
    for (int i = 0; i < 3; i++) {
        int c = tid + i * 256;
        float z = pns[c] * ((v[i] - m) * rs) + pnb[c];
        float x = gp[c];
        float gl = 0.5f * x * (1.f + tanhf(0.7978845608028654f * (x + 0.044715f * x * x * x)));
        g_th[(size_t)row * WID + c] = __float2half_rn(gl * z);
    }
}

// ------------------------- launch --------------------------------------------
extern "C" void kernel_launch(void* const* d_in, const int* in_sizes, int n_in,
                              void* d_out, int out_size)
{
    const float* hidden = (const float*)d_in[0];
    const float* wq  = (const float*)d_in[1];
    const float* wv  = (const float*)d_in[2];
    const float* wo  = (const float*)d_in[3];
    const float* wg  = (const float*)d_in[4];
    const float* cqk = (const float*)d_in[5];
    const float* cqb = (const float*)d_in[6];
    const float* ckk = (const float*)d_in[7];
    const float* ckb = (const float*)d_in[8];
    const float* W1  = (const float*)d_in[9];
    const float* b1  = (const float*)d_in[10];
    const float* tns = (const float*)d_in[11];
    const float* tnb = (const float*)d_in[12];
    const float* lrk = (const float*)d_in[13];
    const float* lrb = (const float*)d_in[14];
    const float* lti = (const float*)d_in[15];
    const float* pns = (const float*)d_in[16];
    const float* pnb = (const float*)d_in[17];
    float* out = (float*)d_out;

    float *p_xqk, *p_xv, *p_gate;
    __half *p_hh, *p_th, *p_wt;
    cudaGetSymbolAddress((void**)&p_xqk,  g_xqk);
    cudaGetSymbolAddress((void**)&p_xv,   g_xv);
    cudaGetSymbolAddress((void**)&p_gate, g_gate);
    cudaGetSymbolAddress((void**)&p_hh,   g_hh);
    cudaGetSymbolAddress((void**)&p_th,   g_th);
    cudaGetSymbolAddress((void**)&p_wt,   g_wt);

    const int smem_mma = 2 * STAGEB;   // 40960
    cudaFuncSetAttribute(mma_gemm_kernel, cudaFuncAttributeMaxDynamicSharedMemorySize, smem_mma);
    cudaFuncSetAttribute(ttt_scan_kernel, cudaFuncAttributeMaxDynamicSharedMemorySize, SCAN_SMEM);

    // 1: lr + weight cvt fused
    prep_kernel<<<2048 + 4 * 576, 256>>>(hidden, lrk, lrb, wq, wv, wg, wo);
    // 2: hidden -> fp16
    cvt_h_kernel<<<(MTOT * WID / 4 + 255) / 256, 256>>>(hidden, p_hh, MTOT * WID / 4);
    // 3: fused QVG GEMM
    {
        dim3 gg(18, MTOT / 128);
        mma_gemm_kernel<<<gg, 256, smem_mma>>>(p_hh, p_wt, p_xqk, p_xv, p_gate);
    }
    // 4: scan — profiled launch
    ttt_scan_kernel<<<Bsz * NH, 256, SCAN_SMEM>>>(W1, b1, tns, tnb, lti, cqk, cqb, ckk, ckb);
    // 5: post LN * gelu gate
    postfuse_kernel<<<MTOT, 256>>>(pns, pnb);
    // 6: output GEMM
    {
        dim3 gg(6, MTOT / 128);
        mma_gemm_kernel<<<gg, 256, smem_mma>>>(p_th, p_wt + (size_t)3 * WW, out, out, out);
    }
}